// round 14
// baseline (speedup 1.0000x reference)
#include <cuda_runtime.h>
#include <cuda_bf16.h>
#include <cuda_fp16.h>
#include <math.h>
#include <stdint.h>

#define S_LEN 2048
#define E_DIM 1024
#define N_HEADS 16
#define HD 64
#define BATCH 2
#define M_ROWS 4096
#define SCALE_Q 0.18033688011112042f   // 0.125 * log2(e)

// ---------------- scratch ---------------------------------------------------
__device__ __align__(256) float g_cos[S_LEN * 32];
__device__ __align__(256) float g_sin[S_LEN * 32];
__device__ __align__(256) float g_bias[3 * E_DIM];
__device__ __align__(256) __half g_xh[(size_t)M_ROWS * E_DIM];          // x fp16
__device__ __align__(256) __half g_ch[(size_t)M_ROWS * E_DIM];          // ctx fp16
__device__ __align__(256) __half g_wth[4][(size_t)E_DIM * E_DIM];       // W^T hi
__device__ __align__(256) __half g_wtl[4][(size_t)E_DIM * E_DIM];       // W^T lo
__device__ __align__(256) __half g_qh2[(size_t)M_ROWS * E_DIM];         // Q hi
__device__ __align__(256) __half g_ql2[(size_t)M_ROWS * E_DIM];         // Q lo
__device__ __align__(256) __half g_kh2[(size_t)M_ROWS * E_DIM];         // K hi
__device__ __align__(256) __half g_kl2[(size_t)M_ROWS * E_DIM];         // K lo
__device__ __align__(256) __half g_vh2[(size_t)M_ROWS * E_DIM];         // V single

// ---------------- helpers ---------------------------------------------------
__device__ __forceinline__ uint32_t smem_u32(const void* p) {
    uint32_t a;
    asm("{ .reg .u64 t; cvta.to.shared.u64 t, %1; cvt.u32.u64 %0, t; }"
        : "=r"(a) : "l"(p));
    return a;
}
__device__ __forceinline__ void ldmatrix_x4(uint32_t* r, uint32_t addr) {
    asm volatile("ldmatrix.sync.aligned.m8n8.x4.shared.b16 {%0,%1,%2,%3}, [%4];"
                 : "=r"(r[0]), "=r"(r[1]), "=r"(r[2]), "=r"(r[3]) : "r"(addr));
}
__device__ __forceinline__ void ldmatrix_x4_trans(uint32_t* r, uint32_t addr) {
    asm volatile("ldmatrix.sync.aligned.m8n8.x4.trans.shared.b16 {%0,%1,%2,%3}, [%4];"
                 : "=r"(r[0]), "=r"(r[1]), "=r"(r[2]), "=r"(r[3]) : "r"(addr));
}
__device__ __forceinline__ void mma16816h(float* c, const uint32_t* a, const uint32_t* b) {
    asm("mma.sync.aligned.m16n8k16.row.col.f32.f16.f16.f32 "
        "{%0,%1,%2,%3}, {%4,%5,%6,%7}, {%8,%9}, {%0,%1,%2,%3};"
        : "+f"(c[0]), "+f"(c[1]), "+f"(c[2]), "+f"(c[3])
        : "r"(a[0]), "r"(a[1]), "r"(a[2]), "r"(a[3]), "r"(b[0]), "r"(b[1]));
}
__device__ __forceinline__ void cp_async16(uint32_t dst, const void* src) {
    asm volatile("cp.async.cg.shared.global [%0], [%1], 16;" :: "r"(dst), "l"(src));
}
__device__ __forceinline__ float ex2(float x) {
    float y;
    asm("ex2.approx.f32 %0, %1;" : "=f"(y) : "f"(x));
    return y;
}
__device__ __forceinline__ void split2h(float x, float y, uint32_t& h, uint32_t& l) {
    __half2 hb = __floats2half2_rn(x, y);
    float2 hf = __half22float2(hb);
    __half2 lb = __floats2half2_rn(x - hf.x, y - hf.y);
    h = *(uint32_t*)&hb;
    l = *(uint32_t*)&lb;
}

// ---------------------------------------------------------------------------
// x: f32 -> fp16; first 256 blocks also build rope tables + staged biases
__global__ void cvt_half_kernel(const float4* __restrict__ src, int n4,
                                const float* __restrict__ bq,
                                const float* __restrict__ bk,
                                const float* __restrict__ bv) {
    int i = blockIdx.x * blockDim.x + threadIdx.x;
    if (i < 3 * E_DIM) {
        const float* b = (i < E_DIM) ? bq : (i < 2 * E_DIM) ? bk : bv;
        g_bias[i] = b[i & (E_DIM - 1)];
    }
    if (i < S_LEN * 32) {
        int s = i >> 5, j = i & 31;
        float inv = (float)pow(10000.0, -(double)j / 32.0);
        float th = (float)s * inv;
        g_cos[i] = cosf(th);
        g_sin[i] = sinf(th);
    }
    if (i >= n4) return;
    float4 v = src[i];
    __half2* dst = (__half2*)g_xh;
    dst[2 * i]     = __floats2half2_rn(v.x, v.y);
    dst[2 * i + 1] = __floats2half2_rn(v.z, v.w);
}

__global__ void cvt_transpose4_kernel(const float* __restrict__ W0,
                                      const float* __restrict__ W1,
                                      const float* __restrict__ W2,
                                      const float* __restrict__ W3) {
    __shared__ float t[32][33];
    const float* Ws[4] = {W0, W1, W2, W3};
    const float* W = Ws[blockIdx.z];
    __half* th = g_wth[blockIdx.z];
    __half* tl = g_wtl[blockIdx.z];
    int bx = blockIdx.x, by = blockIdx.y;
    int tid = threadIdx.x;
#pragma unroll
    for (int it = 0; it < 4; it++) {
        int idx = tid + it * 256;
        int r = idx >> 5, c = idx & 31;
        t[r][c] = W[(size_t)(by * 32 + r) * E_DIM + bx * 32 + c];
    }
    __syncthreads();
#pragma unroll
    for (int it = 0; it < 4; it++) {
        int idx = tid + it * 256;
        int r = idx >> 5, c = idx & 31;
        float x = t[c][r];
        __half h = __float2half_rn(x);
        size_t o = (size_t)(bx * 32 + r) * E_DIM + by * 32 + c;
        th[o] = h;
        tl[o] = __float2half_rn(x - __half2float(h));
    }
}

// ---------------------------------------------------------------------------
// 2-term fp16 GEMM: C = A * (Bhi + Blo). CTA 256x128, BK=64, 8 warps (4x2).
// ---------------------------------------------------------------------------
#define A_TB 36864
#define B_TB 18432
#define BUF_BYTES (A_TB + 2 * B_TB)
#define GSMEM (2 * BUF_BYTES)
#define NCHUNK 16

__device__ __forceinline__ void load_chunk_async(
    const __half* __restrict__ A,
    const __half* __restrict__ Bhi, const __half* __restrict__ Blo,
    int m0, int n0, int k0, uint32_t st, int tid) {
#pragma unroll
    for (int it = 0; it < 8; it++) {
        int idx = tid + it * 256;
        int r = idx >> 3, seg = idx & 7;
        cp_async16(st + (uint32_t)(r * 144 + seg * 16),
                   A + (size_t)(m0 + r) * E_DIM + k0 + seg * 8);
    }
#pragma unroll
    for (int it = 0; it < 4; it++) {
        int idx = tid + it * 256;
        int r = idx >> 3, seg = idx & 7;
        uint32_t off = (uint32_t)(r * 144 + seg * 16);
        const size_t go = (size_t)(n0 + r) * E_DIM + k0 + seg * 8;
        cp_async16(st + A_TB + off, Bhi + go);
        cp_async16(st + A_TB + B_TB + off, Blo + go);
    }
}

__device__ __forceinline__ void gemm_mainloop(
    const __half* __restrict__ A,
    const __half* __restrict__ Bhi, const __half* __restrict__ Blo,
    int m0, int n0, uint32_t sbase, int tid, int wm, int wn, int lane,
    float acc[4][8][4]) {

    load_chunk_async(A, Bhi, Blo, m0, n0, 0, sbase, tid);
    asm volatile("cp.async.commit_group;");

    for (int c = 0; c < NCHUNK; c++) {
        asm volatile("cp.async.wait_group 0;");
        __syncthreads();
        if (c + 1 < NCHUNK) {
            load_chunk_async(A, Bhi, Blo, m0, n0, (c + 1) << 6,
                             sbase + ((c + 1) & 1) * BUF_BYTES, tid);
            asm volatile("cp.async.commit_group;");
        }

        const uint32_t st = sbase + (c & 1) * BUF_BYTES;
        const uint32_t A_s = st;
        const uint32_t Bhi_s = st + A_TB, Blo_s = st + A_TB + B_TB;

#pragma unroll
        for (int ks = 0; ks < 4; ks++) {
            uint32_t af[4][4];
#pragma unroll
            for (int mt = 0; mt < 4; mt++) {
                int row = wm * 64 + mt * 16 + (lane & 15);
                int kb = ks * 16 + ((lane >> 4) << 3);
                ldmatrix_x4(af[mt], A_s + (uint32_t)(row * 144 + kb * 2));
            }
#pragma unroll
            for (int np = 0; np < 4; np++) {
                uint32_t bh[4], bl[4];
                int row = wn * 64 + np * 16 + ((lane >> 4) << 3) + (lane & 7);
                int kb = ks * 16 + (((lane >> 3) & 1) << 3);
                uint32_t off = (uint32_t)(row * 144 + kb * 2);
                ldmatrix_x4(bh, Bhi_s + off);
                ldmatrix_x4(bl, Blo_s + off);
#pragma unroll
                for (int half = 0; half < 2; half++)
#pragma unroll
                    for (int mt = 0; mt < 4; mt++)
                        mma16816h(acc[mt][2 * np + half], af[mt], bh + 2 * half);
#pragma unroll
                for (int half = 0; half < 2; half++)
#pragma unroll
                    for (int mt = 0; mt < 4; mt++)
                        mma16816h(acc[mt][2 * np + half], af[mt], bl + 2 * half);
            }
        }
    }
}

// Fused QKV projection: z = 0:Q(+RoPE+scale) 1:K(+RoPE) 2:V(single)
__global__ __launch_bounds__(256)
void tgemm_qkv_kernel() {
    extern __shared__ __align__(1024) char dsm[];
    const uint32_t sbase = smem_u32(dsm);
    const int tid = threadIdx.x;
    const int wid = tid >> 5, lane = tid & 31;
    const int wm = wid & 3, wn = wid >> 2;
    const int g = lane >> 2, tg = lane & 3;
    const int m0 = blockIdx.y << 8, n0 = blockIdx.x << 7;
    const int z = blockIdx.z;

    const float* bias = g_bias + (z << 10);

    float acc[4][8][4] = {};
    gemm_mainloop(g_xh, g_wth[z], g_wtl[z], m0, n0, sbase, tid, wm, wn, lane, acc);

    const int h = (n0 + wn * 64) >> 6;
#pragma unroll
    for (int mt = 0; mt < 4; mt++) {
#pragma unroll
        for (int h2 = 0; h2 < 2; h2++) {
            int m = m0 + wm * 64 + mt * 16 + g + h2 * 8;
            int bb = m >> 11, s = m & (S_LEN - 1);
            size_t rb = (((size_t)(bb * N_HEADS + h)) * S_LEN + s) << 6;
            float vals[8][2];
#pragma unroll
            for (int nt = 0; nt < 8; nt++) {
                int col = nt * 8 + tg * 2;
                float2 bv = *(const float2*)&bias[n0 + wn * 64 + col];
                vals[nt][0] = acc[mt][nt][h2 * 2 + 0] + bv.x;
                vals[nt][1] = acc[mt][nt][h2 * 2 + 1] + bv.y;
            }
            if (z < 2) {
#pragma unroll
                for (int nt = 0; nt < 4; nt++) {
#pragma unroll
                    for (int jj = 0; jj < 2; jj++) {
                        int d = nt * 8 + tg * 2 + jj;
                        float cth = g_cos[(s << 5) + d];
                        float sth = g_sin[(s << 5) + d];
                        float lo = vals[nt][jj], hi = vals[nt + 4][jj];
                        vals[nt][jj]     = fmaf(lo, cth, -hi * sth);
                        vals[nt + 4][jj] = fmaf(hi, cth,  lo * sth);
                    }
                }
            }
            if (z == 0) {
#pragma unroll
                for (int nt = 0; nt < 8; nt++) {
                    vals[nt][0] *= SCALE_Q;
                    vals[nt][1] *= SCALE_Q;
                }
            }
            if (z == 2) {
#pragma unroll
                for (int nt = 0; nt < 8; nt++) {
                    __half2 hv = __floats2half2_rn(vals[nt][0], vals[nt][1]);
                    *(__half2*)(g_vh2 + rb + nt * 8 + tg * 2) = hv;
                }
            } else {
                __half* Chi = (z == 0) ? g_qh2 : g_kh2;
                __half* Clo = (z == 0) ? g_ql2 : g_kl2;
#pragma unroll
                for (int nt = 0; nt < 8; nt++) {
                    uint32_t hv, lv;
                    split2h(vals[nt][0], vals[nt][1], hv, lv);
                    *(uint32_t*)(Chi + rb + nt * 8 + tg * 2) = hv;
                    *(uint32_t*)(Clo + rb + nt * 8 + tg * 2) = lv;
                }
            }
        }
    }
}

// Output projection
__global__ __launch_bounds__(256)
void tgemm_out_kernel(const float* __restrict__ bias, float* __restrict__ C) {
    extern __shared__ __align__(1024) char dsm[];
    const uint32_t sbase = smem_u32(dsm);
    const int tid = threadIdx.x;
    const int wid = tid >> 5, lane = tid & 31;
    const int wm = wid & 3, wn = wid >> 2;
    const int g = lane >> 2, tg = lane & 3;
    const int m0 = blockIdx.y << 8, n0 = blockIdx.x << 7;

    float acc[4][8][4] = {};
    gemm_mainloop(g_ch, g_wth[3], g_wtl[3], m0, n0, sbase, tid, wm, wn, lane, acc);

#pragma unroll
    for (int mt = 0; mt < 4; mt++) {
#pragma unroll
        for (int h2 = 0; h2 < 2; h2++) {
            int m = m0 + wm * 64 + mt * 16 + g + h2 * 8;
            float* dst = &C[(size_t)m * E_DIM + n0 + wn * 64];
#pragma unroll
            for (int nt = 0; nt < 8; nt++) {
                int col = nt * 8 + tg * 2;
                float2 bv = *(const float2*)&bias[n0 + wn * 64 + col];
                *(float2*)&dst[col] = make_float2(acc[mt][nt][h2 * 2 + 0] + bv.x,
                                                  acc[mt][nt][h2 * 2 + 1] + bv.y);
            }
        }
    }
}

// ---------------------------------------------------------------------------
// Flash attention. Q-tile 128, KV-tile 128, 8 warps.
// QK 3-term fp16, PV 2-term (P regs split x V single). Diagonal-tile work skip.
// grid: x = bh (32), y = reversed q-tile (16) -> heaviest 148 blocks first.
// ---------------------------------------------------------------------------
#define ATT_Q    0
#define ATT_QL   18432
#define ATT_BUF0 36864
#define ATT_BUFSZ 55808
#define ATT_SMEM (36864 + 2 * ATT_BUFSZ)

__device__ __forceinline__ void attn_issue_kv(
    const __half* khi, const __half* klo, const __half* v,
    const int* mask, int mask_off, uint32_t sb, int t, int tid) {
    uint32_t bufb = sb + ATT_BUF0 + (t & 1) * ATT_BUFSZ;
    int k0 = t << 7;
    const __half* srcs[3] = {khi, klo, v};
#pragma unroll
    for (int i = 0; i < 12; i++) {
        int idx = tid + i * 256;
        int arr = idx >> 10;
        int r = (idx >> 3) & 127, seg = idx & 7;
        cp_async16(bufb + arr * 18432 + (uint32_t)(r * 144 + seg * 16),
                   srcs[arr] + (size_t)(k0 + r) * HD + seg * 8);
    }
    if (tid < 32)
        cp_async16(bufb + 55296 + tid * 16, mask + mask_off + k0 + tid * 4);
}

__global__ __launch_bounds__(256)
void attn_kernel(const int* __restrict__ mask) {
    extern __shared__ __align__(1024) char sm_[];
    const uint32_t sb = smem_u32(sm_);
    const int tid = threadIdx.x, w = tid >> 5, lane = tid & 31;
    const int g = lane >> 2, tg = lane & 3;
    const int qt = gridDim.y - 1 - blockIdx.y;
    const int bh = blockIdx.x, bb = bh >> 4, hh = bh & 15;
    const int q0 = qt << 7;
    const size_t base = (size_t)bh * S_LEN * HD;

    {
        const __half* s0 = g_qh2 + base + (size_t)q0 * HD;
        const __half* s1 = g_ql2 + base + (size_t)q0 * HD;
#pragma unroll
        for (int i = 0; i < 8; i++) {
            int idx = tid + i * 256;
            int arr = idx >> 10;
            int r = (idx >> 3) & 127, seg = idx & 7;
            uint4 v = *(const uint4*)((arr ? s1 : s0) + (size_t)r * HD + seg * 8);
            *(uint4*)(sm_ + (arr ? ATT_QL : ATT_Q) + r * 144 + seg * 16) = v;
        }
    }

    const int ntile = qt + 1;
    attn_issue_kv(g_kh2 + base, g_kl2 + base, g_vh2 + base,
                  mask, bb * S_LEN, sb, 0, tid);
    asm volatile("cp.async.commit_group;");
    __syncthreads();

    uint32_t qfh[4][4], qfl[4][4];
    {
        int i = lane & 15;
        int prow = (i < 8) ? (w * 8 + i) : (64 + w * 8 + (i - 8));
        int kb = ((lane >> 4) << 3);
#pragma unroll
        for (int ks = 0; ks < 4; ks++) {
            uint32_t off = (uint32_t)(prow * 144 + (ks * 16 + kb) * 2);
            ldmatrix_x4(qfh[ks], sb + ATT_Q + off);
            ldmatrix_x4(qfl[ks], sb + ATT_QL + off);
        }
    }
    const int row0 = q0 + w * 8 + g;
    const int row1 = q0 + 64 + w * 8 + g;
    // diagonal-tile live bound: columns beyond this warp's max row are dead
    const int diag_lim = ((71 + 8 * w) >> 4) + 1;

    float oacc[8][4] = {};
    float l0 = 0.f, l1 = 0.f, mo0 = -1e30f, mo1 = -1e30f;

    for (int t = 0; t < ntile; t++) {
        asm volatile("cp.async.wait_group 0;");
        __syncthreads();
        if (t + 1 < ntile) {
            attn_issue_kv(g_kh2 + base, g_kl2 + base, g_vh2 + base,
                          mask, bb * S_LEN, sb, t + 1, tid);
            asm volatile("cp.async.commit_group;");
        }
        const uint32_t bufb = sb + ATT_BUF0 + (t & 1) * ATT_BUFSZ;
        const int k0 = t << 7;
        const int lim = (t == ntile - 1) ? diag_lim : 8;

        // S = Q @ K^T (3 terms); sc zero-init covers skipped column tiles
        float sc[16][4] = {};
        for (int ks = 0; ks < 4; ks++) {
            for (int ntp = 0; ntp < lim; ntp++) {
                uint32_t kh[4], kl[4];
                int row = ntp * 16 + ((lane >> 4) << 3) + (lane & 7);
                int kb = ks * 16 + (((lane >> 3) & 1) << 3);
                uint32_t off = (uint32_t)(row * 144 + kb * 2);
                ldmatrix_x4(kh, bufb + off);
                ldmatrix_x4(kl, bufb + 18432 + off);
#pragma unroll
                for (int hf = 0; hf < 2; hf++)
                    mma16816h(sc[2 * ntp + hf], qfh[ks], kh + 2 * hf);
#pragma unroll
                for (int hf = 0; hf < 2; hf++)
                    mma16816h(sc[2 * ntp + hf], qfh[ks], kl + 2 * hf);
#pragma unroll
                for (int hf = 0; hf < 2; hf++)
                    mma16816h(sc[2 * ntp + hf], qfl[ks], kh + 2 * hf);
            }
        }

        const int* Ms = (const int*)(sm_ + ATT_BUF0 + (t & 1) * ATT_BUFSZ + 55296);
        uint32_t pb[4];
        pb[0] = __ballot_sync(0xffffffffu, Ms[lane] != 0);
        pb[1] = __ballot_sync(0xffffffffu, Ms[lane + 32] != 0);
        pb[2] = __ballot_sync(0xffffffffu, Ms[lane + 64] != 0);
        pb[3] = __ballot_sync(0xffffffffu, Ms[lane + 96] != 0);
        if ((pb[0] & pb[1] & pb[2] & pb[3]) != 0xffffffffu) {
#pragma unroll
            for (int nt = 0; nt < 16; nt++)
#pragma unroll
                for (int j = 0; j < 2; j++) {
                    int cl = nt * 8 + tg * 2 + j;
                    if (!((pb[cl >> 5] >> (cl & 31)) & 1)) {
                        sc[nt][j] = -1e30f;
                        sc[nt][2 + j] = -1e30f;
                    }
                }
        }
        if (k0 + 127 > row0) {
#pragma unroll
            for (int nt = 0; nt < 16; nt++)
#pragma unroll
                for (int j = 0; j < 2; j++) {
                    int cg = k0 + nt * 8 + tg * 2 + j;
                    if (cg > row0) sc[nt][j] = -1e30f;
                    if (cg > row1) sc[nt][2 + j] = -1e30f;
                }
        }

        float mx0 = -1e30f, mx1 = -1e30f;
#pragma unroll
        for (int nt = 0; nt < 16; nt++) {
            mx0 = fmaxf(mx0, fmaxf(sc[nt][0], sc[nt][1]));
            mx1 = fmaxf(mx1, fmaxf(sc[nt][2], sc[nt][3]));
        }
        mx0 = fmaxf(mx0, __shfl_xor_sync(0xffffffffu, mx0, 1));
        mx0 = fmaxf(mx0, __shfl_xor_sync(0xffffffffu, mx0, 2));
        mx1 = fmaxf(mx1, __shfl_xor_sync(0xffffffffu, mx1, 1));
        mx1 = fmaxf(mx1, __shfl_xor_sync(0xffffffffu, mx1, 2));
        float mn0 = fmaxf(mo0, mx0), mn1 = fmaxf(mo1, mx1);
        float al0 = ex2(mo0 - mn0), al1 = ex2(mo1 - mn1);
        float rs0 = 0.f, rs1 = 0.f;
#pragma unroll
        for (int nt = 0; nt < 16; nt++) {
            sc[nt][0] = ex2(sc[nt][0] - mn0);
            sc[nt][1] = ex2(sc[nt][1] - mn0);
            sc[nt][2] = ex2(sc[nt][2] - mn1);
            sc[nt][3] = ex2(sc[nt][3] - mn1);
            rs0 += sc[nt][0] + sc[nt][1];
            rs1 += sc[nt][2] + sc[nt][3];
        }
        rs0 += __shfl_xor_sync(0xffffffffu, rs0, 1);
        rs0 += __shfl_xor_sync(0xffffffffu, rs0, 2);
        rs1 += __shfl_xor_sync(0xffffffffu, rs1, 1);
        rs1 += __shfl_xor_sync(0xffffffffu, rs1, 2);
        l0 = l0 * al0 + rs0;
        l1 = l1 * al1 + rs1;
        mo0 = mn0; mo1 = mn1;
#pragma unroll
        for (int nt = 0; nt < 8; nt++) {
            oacc[nt][0] *= al0; oacc[nt][1] *= al0;
            oacc[nt][2] *= al1; oacc[nt][3] *= al1;
        }

        // O += (Phi + Plo) @ V ; skip KV rows with all-zero P on diagonal tile
        for (int ks = 0; ks < lim; ks++) {
            uint32_t pa[4], pl[4];
            split2h(sc[2 * ks][0], sc[2 * ks][1], pa[0], pl[0]);
            split2h(sc[2 * ks][2], sc[2 * ks][3], pa[1], pl[1]);
            split2h(sc[2 * ks + 1][0], sc[2 * ks + 1][1], pa[2], pl[2]);
            split2h(sc[2 * ks + 1][2], sc[2 * ks + 1][3], pa[3], pl[3]);
#pragma unroll
            for (int dtp = 0; dtp < 4; dtp++) {
                uint32_t vh[4];
                int rkv = ks * 16 + ((lane >> 3) & 1) * 8 + (lane & 7);
                int cd = dtp * 16 + (lane >> 4) * 8;
                ldmatrix_x4_trans(vh, bufb + 36864 + (uint32_t)(rkv * 144 + cd * 2));
#pragma unroll
                for (int hf = 0; hf < 2; hf++)
                    mma16816h(oacc[2 * dtp + hf], pa, vh + 2 * hf);
#pragma unroll
                for (int hf = 0; hf < 2; hf++)
                    mma16816h(oacc[2 * dtp + hf], pl, vh + 2 * hf);
            }
        }
    }

    float inv0 = 1.0f / l0, inv1 = 1.0f / l1;
    __half* d0 = g_ch + ((size_t)(bb * S_LEN + row0)) * E_DIM + hh * 64;
    __half* d1 = g_ch + ((size_t)(bb * S_LEN + row1)) * E_DIM + hh * 64;
#pragma unroll
    for (int nt = 0; nt < 8; nt++) {
        int d = nt * 8 + tg * 2;
        *(__half2*)(d0 + d) = __floats2half2_rn(oacc[nt][0] * inv0, oacc[nt][1] * inv0);
        *(__half2*)(d1 + d) = __floats2half2_rn(oacc[nt][2] * inv1, oacc[nt][3] * inv1);
    }
}

// ---------------------------------------------------------------------------
extern "C" void kernel_launch(void* const* d_in, const int* in_sizes, int n_in,
                              void* d_out, int out_size) {
    const float* x    = (const float*)d_in[0];
    const int*   mask = (const int*)d_in[1];
    const float* Wq   = (const float*)d_in[2];
    const float* bq   = (const float*)d_in[3];
    const float* Wk   = (const float*)d_in[4];
    const float* bk   = (const float*)d_in[5];
    const float* Wv   = (const float*)d_in[6];
    const float* bv   = (const float*)d_in[7];
    const float* Wo   = (const float*)d_in[8];
    const float* bo   = (const float*)d_in[9];
    float* out = (float*)d_out;

    cvt_transpose4_kernel<<<dim3(32, 32, 4), 256>>>(Wq, Wk, Wv, Wo);

    const int n4 = M_ROWS * E_DIM / 4;
    cvt_half_kernel<<<(n4 + 255) / 256, 256>>>((const float4*)x, n4, bq, bk, bv);

    cudaFuncSetAttribute(tgemm_qkv_kernel, cudaFuncAttributeMaxDynamicSharedMemorySize, GSMEM);
    cudaFuncSetAttribute(tgemm_out_kernel, cudaFuncAttributeMaxDynamicSharedMemorySize, GSMEM);
    cudaFuncSetAttribute(attn_kernel, cudaFuncAttributeMaxDynamicSharedMemorySize, ATT_SMEM);

    tgemm_qkv_kernel<<<dim3(E_DIM / 128, M_ROWS / 256, 3), 256, GSMEM>>>();

    attn_kernel<<<dim3(BATCH * N_HEADS, S_LEN / 128), 256, ATT_SMEM>>>(mask);

    tgemm_out_kernel<<<dim3(E_DIM / 128, M_ROWS / 256), 256, GSMEM>>>(bo, out);
}

// round 15
// speedup vs baseline: 1.3157x; 1.3157x over previous
#include <cuda_runtime.h>
#include <cuda_bf16.h>
#include <cuda_fp16.h>
#include <math.h>
#include <stdint.h>

#define S_LEN 2048
#define E_DIM 1024
#define N_HEADS 16
#define HD 64
#define BATCH 2
#define M_ROWS 4096
#define SCALE_Q 0.18033688011112042f   // 0.125 * log2(e)

// ---------------- scratch ---------------------------------------------------
__device__ __align__(256) float g_cos[S_LEN * 32];
__device__ __align__(256) float g_sin[S_LEN * 32];
__device__ __align__(256) float g_bias[3 * E_DIM];
__device__ __align__(256) __half g_xh[(size_t)M_ROWS * E_DIM];          // x fp16
__device__ __align__(256) __half g_ch[(size_t)M_ROWS * E_DIM];          // ctx fp16
__device__ __align__(256) __half g_wth[4][(size_t)E_DIM * E_DIM];       // W^T hi
__device__ __align__(256) __half g_wtl[4][(size_t)E_DIM * E_DIM];       // W^T lo
__device__ __align__(256) __half g_qh2[(size_t)M_ROWS * E_DIM];         // Q hi
__device__ __align__(256) __half g_ql2[(size_t)M_ROWS * E_DIM];         // Q lo
__device__ __align__(256) __half g_kh2[(size_t)M_ROWS * E_DIM];         // K hi
__device__ __align__(256) __half g_kl2[(size_t)M_ROWS * E_DIM];         // K lo
__device__ __align__(256) __half g_vh2[(size_t)M_ROWS * E_DIM];         // V single

// ---------------- helpers ---------------------------------------------------
__device__ __forceinline__ uint32_t smem_u32(const void* p) {
    uint32_t a;
    asm("{ .reg .u64 t; cvta.to.shared.u64 t, %1; cvt.u32.u64 %0, t; }"
        : "=r"(a) : "l"(p));
    return a;
}
__device__ __forceinline__ void ldmatrix_x4(uint32_t* r, uint32_t addr) {
    asm volatile("ldmatrix.sync.aligned.m8n8.x4.shared.b16 {%0,%1,%2,%3}, [%4];"
                 : "=r"(r[0]), "=r"(r[1]), "=r"(r[2]), "=r"(r[3]) : "r"(addr));
}
__device__ __forceinline__ void ldmatrix_x4_trans(uint32_t* r, uint32_t addr) {
    asm volatile("ldmatrix.sync.aligned.m8n8.x4.trans.shared.b16 {%0,%1,%2,%3}, [%4];"
                 : "=r"(r[0]), "=r"(r[1]), "=r"(r[2]), "=r"(r[3]) : "r"(addr));
}
__device__ __forceinline__ void mma16816h(float* c, const uint32_t* a, const uint32_t* b) {
    asm("mma.sync.aligned.m16n8k16.row.col.f32.f16.f16.f32 "
        "{%0,%1,%2,%3}, {%4,%5,%6,%7}, {%8,%9}, {%0,%1,%2,%3};"
        : "+f"(c[0]), "+f"(c[1]), "+f"(c[2]), "+f"(c[3])
        : "r"(a[0]), "r"(a[1]), "r"(a[2]), "r"(a[3]), "r"(b[0]), "r"(b[1]));
}
__device__ __forceinline__ void cp_async16(uint32_t dst, const void* src) {
    asm volatile("cp.async.cg.shared.global [%0], [%1], 16;" :: "r"(dst), "l"(src));
}
__device__ __forceinline__ float ex2(float x) {
    float y;
    asm("ex2.approx.f32 %0, %1;" : "=f"(y) : "f"(x));
    return y;
}
__device__ __forceinline__ void split2h(float x, float y, uint32_t& h, uint32_t& l) {
    __half2 hb = __floats2half2_rn(x, y);
    float2 hf = __half22float2(hb);
    __half2 lb = __floats2half2_rn(x - hf.x, y - hf.y);
    h = *(uint32_t*)&hb;
    l = *(uint32_t*)&lb;
}

// ---------------------------------------------------------------------------
// x: f32 -> fp16; low blocks also build rope tables + staged biases
__global__ void cvt_half_kernel(const float4* __restrict__ src, int n4,
                                const float* __restrict__ bq,
                                const float* __restrict__ bk,
                                const float* __restrict__ bv) {
    int i = blockIdx.x * blockDim.x + threadIdx.x;
    if (i < 3 * E_DIM) {
        const float* b = (i < E_DIM) ? bq : (i < 2 * E_DIM) ? bk : bv;
        g_bias[i] = b[i & (E_DIM - 1)];
    }
    if (i < S_LEN * 32) {
        int s = i >> 5, j = i & 31;
        float inv = (float)pow(10000.0, -(double)j / 32.0);
        float th = (float)s * inv;
        g_cos[i] = cosf(th);
        g_sin[i] = sinf(th);
    }
    if (i >= n4) return;
    float4 v = src[i];
    __half2* dst = (__half2*)g_xh;
    dst[2 * i]     = __floats2half2_rn(v.x, v.y);
    dst[2 * i + 1] = __floats2half2_rn(v.z, v.w);
}

__global__ void cvt_transpose4_kernel(const float* __restrict__ W0,
                                      const float* __restrict__ W1,
                                      const float* __restrict__ W2,
                                      const float* __restrict__ W3) {
    __shared__ float t[32][33];
    const float* Ws[4] = {W0, W1, W2, W3};
    const float* W = Ws[blockIdx.z];
    __half* th = g_wth[blockIdx.z];
    __half* tl = g_wtl[blockIdx.z];
    int bx = blockIdx.x, by = blockIdx.y;
    int tid = threadIdx.x;
#pragma unroll
    for (int it = 0; it < 4; it++) {
        int idx = tid + it * 256;
        int r = idx >> 5, c = idx & 31;
        t[r][c] = W[(size_t)(by * 32 + r) * E_DIM + bx * 32 + c];
    }
    __syncthreads();
#pragma unroll
    for (int it = 0; it < 4; it++) {
        int idx = tid + it * 256;
        int r = idx >> 5, c = idx & 31;
        float x = t[c][r];
        __half h = __float2half_rn(x);
        size_t o = (size_t)(bx * 32 + r) * E_DIM + by * 32 + c;
        th[o] = h;
        tl[o] = __float2half_rn(x - __half2float(h));
    }
}

// ---------------------------------------------------------------------------
// 2-term fp16 GEMM: C = A * (Bhi + Blo). CTA 256x128, BK=64, 8 warps (4x2).
// ---------------------------------------------------------------------------
#define A_TB 36864
#define B_TB 18432
#define BUF_BYTES (A_TB + 2 * B_TB)
#define GSMEM (2 * BUF_BYTES)
#define NCHUNK 16

__device__ __forceinline__ void load_chunk_async(
    const __half* __restrict__ A,
    const __half* __restrict__ Bhi, const __half* __restrict__ Blo,
    int m0, int n0, int k0, uint32_t st, int tid) {
#pragma unroll
    for (int it = 0; it < 8; it++) {
        int idx = tid + it * 256;
        int r = idx >> 3, seg = idx & 7;
        cp_async16(st + (uint32_t)(r * 144 + seg * 16),
                   A + (size_t)(m0 + r) * E_DIM + k0 + seg * 8);
    }
#pragma unroll
    for (int it = 0; it < 4; it++) {
        int idx = tid + it * 256;
        int r = idx >> 3, seg = idx & 7;
        uint32_t off = (uint32_t)(r * 144 + seg * 16);
        const size_t go = (size_t)(n0 + r) * E_DIM + k0 + seg * 8;
        cp_async16(st + A_TB + off, Bhi + go);
        cp_async16(st + A_TB + B_TB + off, Blo + go);
    }
}

__device__ __forceinline__ void gemm_mainloop(
    const __half* __restrict__ A,
    const __half* __restrict__ Bhi, const __half* __restrict__ Blo,
    int m0, int n0, uint32_t sbase, int tid, int wm, int wn, int lane,
    float acc[4][8][4]) {

    load_chunk_async(A, Bhi, Blo, m0, n0, 0, sbase, tid);
    asm volatile("cp.async.commit_group;");

    for (int c = 0; c < NCHUNK; c++) {
        asm volatile("cp.async.wait_group 0;");
        __syncthreads();
        if (c + 1 < NCHUNK) {
            load_chunk_async(A, Bhi, Blo, m0, n0, (c + 1) << 6,
                             sbase + ((c + 1) & 1) * BUF_BYTES, tid);
            asm volatile("cp.async.commit_group;");
        }

        const uint32_t st = sbase + (c & 1) * BUF_BYTES;
        const uint32_t A_s = st;
        const uint32_t Bhi_s = st + A_TB, Blo_s = st + A_TB + B_TB;

#pragma unroll
        for (int ks = 0; ks < 4; ks++) {
            uint32_t af[4][4];
#pragma unroll
            for (int mt = 0; mt < 4; mt++) {
                int row = wm * 64 + mt * 16 + (lane & 15);
                int kb = ks * 16 + ((lane >> 4) << 3);
                ldmatrix_x4(af[mt], A_s + (uint32_t)(row * 144 + kb * 2));
            }
#pragma unroll
            for (int np = 0; np < 4; np++) {
                uint32_t bh[4], bl[4];
                int row = wn * 64 + np * 16 + ((lane >> 4) << 3) + (lane & 7);
                int kb = ks * 16 + (((lane >> 3) & 1) << 3);
                uint32_t off = (uint32_t)(row * 144 + kb * 2);
                ldmatrix_x4(bh, Bhi_s + off);
                ldmatrix_x4(bl, Blo_s + off);
#pragma unroll
                for (int half = 0; half < 2; half++)
#pragma unroll
                    for (int mt = 0; mt < 4; mt++)
                        mma16816h(acc[mt][2 * np + half], af[mt], bh + 2 * half);
#pragma unroll
                for (int half = 0; half < 2; half++)
#pragma unroll
                    for (int mt = 0; mt < 4; mt++)
                        mma16816h(acc[mt][2 * np + half], af[mt], bl + 2 * half);
            }
        }
    }
}

// Fused QKV projection: z = 0:Q(+RoPE+scale) 1:K(+RoPE) 2:V(single)
__global__ __launch_bounds__(256)
void tgemm_qkv_kernel() {
    extern __shared__ __align__(1024) char dsm[];
    const uint32_t sbase = smem_u32(dsm);
    const int tid = threadIdx.x;
    const int wid = tid >> 5, lane = tid & 31;
    const int wm = wid & 3, wn = wid >> 2;
    const int g = lane >> 2, tg = lane & 3;
    const int m0 = blockIdx.y << 8, n0 = blockIdx.x << 7;
    const int z = blockIdx.z;

    const float* bias = g_bias + (z << 10);

    float acc[4][8][4] = {};
    gemm_mainloop(g_xh, g_wth[z], g_wtl[z], m0, n0, sbase, tid, wm, wn, lane, acc);

    const int h = (n0 + wn * 64) >> 6;
#pragma unroll
    for (int mt = 0; mt < 4; mt++) {
#pragma unroll
        for (int h2 = 0; h2 < 2; h2++) {
            int m = m0 + wm * 64 + mt * 16 + g + h2 * 8;
            int bb = m >> 11, s = m & (S_LEN - 1);
            size_t rb = (((size_t)(bb * N_HEADS + h)) * S_LEN + s) << 6;
            float vals[8][2];
#pragma unroll
            for (int nt = 0; nt < 8; nt++) {
                int col = nt * 8 + tg * 2;
                float2 bv = *(const float2*)&bias[n0 + wn * 64 + col];
                vals[nt][0] = acc[mt][nt][h2 * 2 + 0] + bv.x;
                vals[nt][1] = acc[mt][nt][h2 * 2 + 1] + bv.y;
            }
            if (z < 2) {
#pragma unroll
                for (int nt = 0; nt < 4; nt++) {
#pragma unroll
                    for (int jj = 0; jj < 2; jj++) {
                        int d = nt * 8 + tg * 2 + jj;
                        float cth = g_cos[(s << 5) + d];
                        float sth = g_sin[(s << 5) + d];
                        float lo = vals[nt][jj], hi = vals[nt + 4][jj];
                        vals[nt][jj]     = fmaf(lo, cth, -hi * sth);
                        vals[nt + 4][jj] = fmaf(hi, cth,  lo * sth);
                    }
                }
            }
            if (z == 0) {
#pragma unroll
                for (int nt = 0; nt < 8; nt++) {
                    vals[nt][0] *= SCALE_Q;
                    vals[nt][1] *= SCALE_Q;
                }
            }
            if (z == 2) {
#pragma unroll
                for (int nt = 0; nt < 8; nt++) {
                    __half2 hv = __floats2half2_rn(vals[nt][0], vals[nt][1]);
                    *(__half2*)(g_vh2 + rb + nt * 8 + tg * 2) = hv;
                }
            } else {
                __half* Chi = (z == 0) ? g_qh2 : g_kh2;
                __half* Clo = (z == 0) ? g_ql2 : g_kl2;
#pragma unroll
                for (int nt = 0; nt < 8; nt++) {
                    uint32_t hv, lv;
                    split2h(vals[nt][0], vals[nt][1], hv, lv);
                    *(uint32_t*)(Chi + rb + nt * 8 + tg * 2) = hv;
                    *(uint32_t*)(Clo + rb + nt * 8 + tg * 2) = lv;
                }
            }
        }
    }
}

// Output projection
__global__ __launch_bounds__(256)
void tgemm_out_kernel(const float* __restrict__ bias, float* __restrict__ C) {
    extern __shared__ __align__(1024) char dsm[];
    const uint32_t sbase = smem_u32(dsm);
    const int tid = threadIdx.x;
    const int wid = tid >> 5, lane = tid & 31;
    const int wm = wid & 3, wn = wid >> 2;
    const int g = lane >> 2, tg = lane & 3;
    const int m0 = blockIdx.y << 8, n0 = blockIdx.x << 7;

    float acc[4][8][4] = {};
    gemm_mainloop(g_ch, g_wth[3], g_wtl[3], m0, n0, sbase, tid, wm, wn, lane, acc);

#pragma unroll
    for (int mt = 0; mt < 4; mt++) {
#pragma unroll
        for (int h2 = 0; h2 < 2; h2++) {
            int m = m0 + wm * 64 + mt * 16 + g + h2 * 8;
            float* dst = &C[(size_t)m * E_DIM + n0 + wn * 64];
#pragma unroll
            for (int nt = 0; nt < 8; nt++) {
                int col = nt * 8 + tg * 2;
                float2 bv = *(const float2*)&bias[n0 + wn * 64 + col];
                *(float2*)&dst[col] = make_float2(acc[mt][nt][h2 * 2 + 0] + bv.x,
                                                  acc[mt][nt][h2 * 2 + 1] + bv.y);
            }
        }
    }
}

// ---------------------------------------------------------------------------
// Flash attention (R13-proven): Q-tile 128, KV-tile 128, 8 warps, fully
// unrolled MMA loops. QK 3-term fp16; PV 2-term (P regs split x V single).
// ---------------------------------------------------------------------------
#define ATT_Q    0
#define ATT_QL   18432
#define ATT_BUF0 36864
#define ATT_BUFSZ 55808
#define ATT_SMEM (36864 + 2 * ATT_BUFSZ)

__device__ __forceinline__ void attn_issue_kv(
    const __half* khi, const __half* klo, const __half* v,
    const int* mask, int mask_off, uint32_t sb, int t, int tid) {
    uint32_t bufb = sb + ATT_BUF0 + (t & 1) * ATT_BUFSZ;
    int k0 = t << 7;
    const __half* srcs[3] = {khi, klo, v};
#pragma unroll
    for (int i = 0; i < 12; i++) {
        int idx = tid + i * 256;
        int arr = idx >> 10;
        int r = (idx >> 3) & 127, seg = idx & 7;
        cp_async16(bufb + arr * 18432 + (uint32_t)(r * 144 + seg * 16),
                   srcs[arr] + (size_t)(k0 + r) * HD + seg * 8);
    }
    if (tid < 32)
        cp_async16(bufb + 55296 + tid * 16, mask + mask_off + k0 + tid * 4);
}

__global__ __launch_bounds__(256)
void attn_kernel(const int* __restrict__ mask) {
    extern __shared__ __align__(1024) char sm_[];
    const uint32_t sb = smem_u32(sm_);
    const int tid = threadIdx.x, w = tid >> 5, lane = tid & 31;
    const int g = lane >> 2, tg = lane & 3;
    const int qt = gridDim.x - 1 - blockIdx.x;
    const int bh = blockIdx.y, bb = bh >> 4, hh = bh & 15;
    const int q0 = qt << 7;
    const size_t base = (size_t)bh * S_LEN * HD;

    {
        const __half* s0 = g_qh2 + base + (size_t)q0 * HD;
        const __half* s1 = g_ql2 + base + (size_t)q0 * HD;
#pragma unroll
        for (int i = 0; i < 8; i++) {
            int idx = tid + i * 256;
            int arr = idx >> 10;
            int r = (idx >> 3) & 127, seg = idx & 7;
            uint4 v = *(const uint4*)((arr ? s1 : s0) + (size_t)r * HD + seg * 8);
            *(uint4*)(sm_ + (arr ? ATT_QL : ATT_Q) + r * 144 + seg * 16) = v;
        }
    }

    const int ntile = qt + 1;
    attn_issue_kv(g_kh2 + base, g_kl2 + base, g_vh2 + base,
                  mask, bb * S_LEN, sb, 0, tid);
    asm volatile("cp.async.commit_group;");
    __syncthreads();

    uint32_t qfh[4][4], qfl[4][4];
    {
        int i = lane & 15;
        int prow = (i < 8) ? (w * 8 + i) : (64 + w * 8 + (i - 8));
        int kb = ((lane >> 4) << 3);
#pragma unroll
        for (int ks = 0; ks < 4; ks++) {
            uint32_t off = (uint32_t)(prow * 144 + (ks * 16 + kb) * 2);
            ldmatrix_x4(qfh[ks], sb + ATT_Q + off);
            ldmatrix_x4(qfl[ks], sb + ATT_QL + off);
        }
    }
    const int row0 = q0 + w * 8 + g;
    const int row1 = q0 + 64 + w * 8 + g;

    float oacc[8][4] = {};
    float l0 = 0.f, l1 = 0.f, mo0 = -1e30f, mo1 = -1e30f;

    for (int t = 0; t < ntile; t++) {
        asm volatile("cp.async.wait_group 0;");
        __syncthreads();
        if (t + 1 < ntile) {
            attn_issue_kv(g_kh2 + base, g_kl2 + base, g_vh2 + base,
                          mask, bb * S_LEN, sb, t + 1, tid);
            asm volatile("cp.async.commit_group;");
        }
        const uint32_t bufb = sb + ATT_BUF0 + (t & 1) * ATT_BUFSZ;
        const int k0 = t << 7;

        // S = Q @ K^T (3 terms, fully unrolled)
        float sc[16][4] = {};
#pragma unroll
        for (int ks = 0; ks < 4; ks++) {
#pragma unroll
            for (int ntp = 0; ntp < 8; ntp++) {
                uint32_t kh[4], kl[4];
                int row = ntp * 16 + ((lane >> 4) << 3) + (lane & 7);
                int kb = ks * 16 + (((lane >> 3) & 1) << 3);
                uint32_t off = (uint32_t)(row * 144 + kb * 2);
                ldmatrix_x4(kh, bufb + off);
                ldmatrix_x4(kl, bufb + 18432 + off);
#pragma unroll
                for (int hf = 0; hf < 2; hf++)
                    mma16816h(sc[2 * ntp + hf], qfh[ks], kh + 2 * hf);
#pragma unroll
                for (int hf = 0; hf < 2; hf++)
                    mma16816h(sc[2 * ntp + hf], qfh[ks], kl + 2 * hf);
#pragma unroll
                for (int hf = 0; hf < 2; hf++)
                    mma16816h(sc[2 * ntp + hf], qfl[ks], kh + 2 * hf);
            }
        }

        const int* Ms = (const int*)(sm_ + ATT_BUF0 + (t & 1) * ATT_BUFSZ + 55296);
        uint32_t pb[4];
        pb[0] = __ballot_sync(0xffffffffu, Ms[lane] != 0);
        pb[1] = __ballot_sync(0xffffffffu, Ms[lane + 32] != 0);
        pb[2] = __ballot_sync(0xffffffffu, Ms[lane + 64] != 0);
        pb[3] = __ballot_sync(0xffffffffu, Ms[lane + 96] != 0);
        if ((pb[0] & pb[1] & pb[2] & pb[3]) != 0xffffffffu) {
#pragma unroll
            for (int nt = 0; nt < 16; nt++)
#pragma unroll
                for (int j = 0; j < 2; j++) {
                    int cl = nt * 8 + tg * 2 + j;
                    if (!((pb[cl >> 5] >> (cl & 31)) & 1)) {
                        sc[nt][j] = -1e30f;
                        sc[nt][2 + j] = -1e30f;
                    }
                }
        }
        if (k0 + 127 > row0) {
#pragma unroll
            for (int nt = 0; nt < 16; nt++)
#pragma unroll
                for (int j = 0; j < 2; j++) {
                    int cg = k0 + nt * 8 + tg * 2 + j;
                    if (cg > row0) sc[nt][j] = -1e30f;
                    if (cg > row1) sc[nt][2 + j] = -1e30f;
                }
        }

        float mx0 = -1e30f, mx1 = -1e30f;
#pragma unroll
        for (int nt = 0; nt < 16; nt++) {
            mx0 = fmaxf(mx0, fmaxf(sc[nt][0], sc[nt][1]));
            mx1 = fmaxf(mx1, fmaxf(sc[nt][2], sc[nt][3]));
        }
        mx0 = fmaxf(mx0, __shfl_xor_sync(0xffffffffu, mx0, 1));
        mx0 = fmaxf(mx0, __shfl_xor_sync(0xffffffffu, mx0, 2));
        mx1 = fmaxf(mx1, __shfl_xor_sync(0xffffffffu, mx1, 1));
        mx1 = fmaxf(mx1, __shfl_xor_sync(0xffffffffu, mx1, 2));
        float mn0 = fmaxf(mo0, mx0), mn1 = fmaxf(mo1, mx1);
        float al0 = ex2(mo0 - mn0), al1 = ex2(mo1 - mn1);
        float rs0 = 0.f, rs1 = 0.f;
#pragma unroll
        for (int nt = 0; nt < 16; nt++) {
            sc[nt][0] = ex2(sc[nt][0] - mn0);
            sc[nt][1] = ex2(sc[nt][1] - mn0);
            sc[nt][2] = ex2(sc[nt][2] - mn1);
            sc[nt][3] = ex2(sc[nt][3] - mn1);
            rs0 += sc[nt][0] + sc[nt][1];
            rs1 += sc[nt][2] + sc[nt][3];
        }
        rs0 += __shfl_xor_sync(0xffffffffu, rs0, 1);
        rs0 += __shfl_xor_sync(0xffffffffu, rs0, 2);
        rs1 += __shfl_xor_sync(0xffffffffu, rs1, 1);
        rs1 += __shfl_xor_sync(0xffffffffu, rs1, 2);
        l0 = l0 * al0 + rs0;
        l1 = l1 * al1 + rs1;
        mo0 = mn0; mo1 = mn1;
#pragma unroll
        for (int nt = 0; nt < 8; nt++) {
            oacc[nt][0] *= al0; oacc[nt][1] *= al0;
            oacc[nt][2] *= al1; oacc[nt][3] *= al1;
        }

        // O += (Phi + Plo) @ V (V single fp16, fully unrolled)
#pragma unroll
        for (int ks = 0; ks < 8; ks++) {
            uint32_t pa[4], pl[4];
            split2h(sc[2 * ks][0], sc[2 * ks][1], pa[0], pl[0]);
            split2h(sc[2 * ks][2], sc[2 * ks][3], pa[1], pl[1]);
            split2h(sc[2 * ks + 1][0], sc[2 * ks + 1][1], pa[2], pl[2]);
            split2h(sc[2 * ks + 1][2], sc[2 * ks + 1][3], pa[3], pl[3]);
#pragma unroll
            for (int dtp = 0; dtp < 4; dtp++) {
                uint32_t vh[4];
                int rkv = ks * 16 + ((lane >> 3) & 1) * 8 + (lane & 7);
                int cd = dtp * 16 + (lane >> 4) * 8;
                ldmatrix_x4_trans(vh, bufb + 36864 + (uint32_t)(rkv * 144 + cd * 2));
#pragma unroll
                for (int hf = 0; hf < 2; hf++)
                    mma16816h(oacc[2 * dtp + hf], pa, vh + 2 * hf);
#pragma unroll
                for (int hf = 0; hf < 2; hf++)
                    mma16816h(oacc[2 * dtp + hf], pl, vh + 2 * hf);
            }
        }
    }

    float inv0 = 1.0f / l0, inv1 = 1.0f / l1;
    __half* d0 = g_ch + ((size_t)(bb * S_LEN + row0)) * E_DIM + hh * 64;
    __half* d1 = g_ch + ((size_t)(bb * S_LEN + row1)) * E_DIM + hh * 64;
#pragma unroll
    for (int nt = 0; nt < 8; nt++) {
        int d = nt * 8 + tg * 2;
        *(__half2*)(d0 + d) = __floats2half2_rn(oacc[nt][0] * inv0, oacc[nt][1] * inv0);
        *(__half2*)(d1 + d) = __floats2half2_rn(oacc[nt][2] * inv1, oacc[nt][3] * inv1);
    }
}

// ---------------------------------------------------------------------------
extern "C" void kernel_launch(void* const* d_in, const int* in_sizes, int n_in,
                              void* d_out, int out_size) {
    const float* x    = (const float*)d_in[0];
    const int*   mask = (const int*)d_in[1];
    const float* Wq   = (const float*)d_in[2];
    const float* bq   = (const float*)d_in[3];
    const float* Wk   = (const float*)d_in[4];
    const float* bk   = (const float*)d_in[5];
    const float* Wv   = (const float*)d_in[6];
    const float* bv   = (const float*)d_in[7];
    const float* Wo   = (const float*)d_in[8];
    const float* bo   = (const float*)d_in[9];
    float* out = (float*)d_out;

    cvt_transpose4_kernel<<<dim3(32, 32, 4), 256>>>(Wq, Wk, Wv, Wo);

    const int n4 = M_ROWS * E_DIM / 4;
    cvt_half_kernel<<<(n4 + 255) / 256, 256>>>((const float4*)x, n4, bq, bk, bv);

    cudaFuncSetAttribute(tgemm_qkv_kernel, cudaFuncAttributeMaxDynamicSharedMemorySize, GSMEM);
    cudaFuncSetAttribute(tgemm_out_kernel, cudaFuncAttributeMaxDynamicSharedMemorySize, GSMEM);
    cudaFuncSetAttribute(attn_kernel, cudaFuncAttributeMaxDynamicSharedMemorySize, ATT_SMEM);

    tgemm_qkv_kernel<<<dim3(E_DIM / 128, M_ROWS / 256, 3), 256, GSMEM>>>();

    attn_kernel<<<dim3(S_LEN / 128, BATCH * N_HEADS), 256, ATT_SMEM>>>(mask);

    tgemm_out_kernel<<<dim3(E_DIM / 128, M_ROWS / 256), 256, GSMEM>>>(bo, out);
}

// round 16
// speedup vs baseline: 1.3993x; 1.0635x over previous
#include <cuda_runtime.h>
#include <cuda_bf16.h>
#include <cuda_fp16.h>
#include <math.h>
#include <stdint.h>

#define S_LEN 2048
#define E_DIM 1024
#define N_HEADS 16
#define HD 64
#define BATCH 2
#define M_ROWS 4096
#define SCALE_Q 0.18033688011112042f   // 0.125 * log2(e)

// ---------------- scratch ---------------------------------------------------
__device__ __align__(256) float g_cos[S_LEN * 32];
__device__ __align__(256) float g_sin[S_LEN * 32];
__device__ __align__(256) float g_bias[3 * E_DIM];
__device__ __align__(256) __half g_xh[(size_t)M_ROWS * E_DIM];          // x fp16
__device__ __align__(256) __half g_ch[(size_t)M_ROWS * E_DIM];          // ctx fp16
__device__ __align__(256) __half g_wth[4][(size_t)E_DIM * E_DIM];       // W^T hi
__device__ __align__(256) __half g_wtl[4][(size_t)E_DIM * E_DIM];       // W^T lo
__device__ __align__(256) __half g_qh2[(size_t)M_ROWS * E_DIM];         // Q hi
__device__ __align__(256) __half g_ql2[(size_t)M_ROWS * E_DIM];         // Q lo
__device__ __align__(256) __half g_kh2[(size_t)M_ROWS * E_DIM];         // K hi
__device__ __align__(256) __half g_kl2[(size_t)M_ROWS * E_DIM];         // K lo
__device__ __align__(256) __half g_vh2[(size_t)M_ROWS * E_DIM];         // V single

// ---------------- helpers ---------------------------------------------------
__device__ __forceinline__ uint32_t smem_u32(const void* p) {
    uint32_t a;
    asm("{ .reg .u64 t; cvta.to.shared.u64 t, %1; cvt.u32.u64 %0, t; }"
        : "=r"(a) : "l"(p));
    return a;
}
__device__ __forceinline__ void ldmatrix_x4(uint32_t* r, uint32_t addr) {
    asm volatile("ldmatrix.sync.aligned.m8n8.x4.shared.b16 {%0,%1,%2,%3}, [%4];"
                 : "=r"(r[0]), "=r"(r[1]), "=r"(r[2]), "=r"(r[3]) : "r"(addr));
}
__device__ __forceinline__ void ldmatrix_x4_trans(uint32_t* r, uint32_t addr) {
    asm volatile("ldmatrix.sync.aligned.m8n8.x4.trans.shared.b16 {%0,%1,%2,%3}, [%4];"
                 : "=r"(r[0]), "=r"(r[1]), "=r"(r[2]), "=r"(r[3]) : "r"(addr));
}
__device__ __forceinline__ void mma16816h(float* c, const uint32_t* a, const uint32_t* b) {
    asm("mma.sync.aligned.m16n8k16.row.col.f32.f16.f16.f32 "
        "{%0,%1,%2,%3}, {%4,%5,%6,%7}, {%8,%9}, {%0,%1,%2,%3};"
        : "+f"(c[0]), "+f"(c[1]), "+f"(c[2]), "+f"(c[3])
        : "r"(a[0]), "r"(a[1]), "r"(a[2]), "r"(a[3]), "r"(b[0]), "r"(b[1]));
}
__device__ __forceinline__ void cp_async16(uint32_t dst, const void* src) {
    asm volatile("cp.async.cg.shared.global [%0], [%1], 16;" :: "r"(dst), "l"(src));
}
__device__ __forceinline__ float ex2(float x) {
    float y;
    asm("ex2.approx.f32 %0, %1;" : "=f"(y) : "f"(x));
    return y;
}
__device__ __forceinline__ void split2h(float x, float y, uint32_t& h, uint32_t& l) {
    __half2 hb = __floats2half2_rn(x, y);
    float2 hf = __half22float2(hb);
    __half2 lb = __floats2half2_rn(x - hf.x, y - hf.y);
    h = *(uint32_t*)&hb;
    l = *(uint32_t*)&lb;
}
__device__ __forceinline__ uint32_t pack2h(float x, float y) {
    __half2 hb = __floats2half2_rn(x, y);
    return *(uint32_t*)&hb;
}

// ---------------------------------------------------------------------------
// x: f32 -> fp16; low blocks also build rope tables + staged biases
__global__ void cvt_half_kernel(const float4* __restrict__ src, int n4,
                                const float* __restrict__ bq,
                                const float* __restrict__ bk,
                                const float* __restrict__ bv) {
    int i = blockIdx.x * blockDim.x + threadIdx.x;
    if (i < 3 * E_DIM) {
        const float* b = (i < E_DIM) ? bq : (i < 2 * E_DIM) ? bk : bv;
        g_bias[i] = b[i & (E_DIM - 1)];
    }
    if (i < S_LEN * 32) {
        int s = i >> 5, j = i & 31;
        float inv = (float)pow(10000.0, -(double)j / 32.0);
        float th = (float)s * inv;
        g_cos[i] = cosf(th);
        g_sin[i] = sinf(th);
    }
    if (i >= n4) return;
    float4 v = src[i];
    __half2* dst = (__half2*)g_xh;
    dst[2 * i]     = __floats2half2_rn(v.x, v.y);
    dst[2 * i + 1] = __floats2half2_rn(v.z, v.w);
}

__global__ void cvt_transpose4_kernel(const float* __restrict__ W0,
                                      const float* __restrict__ W1,
                                      const float* __restrict__ W2,
                                      const float* __restrict__ W3) {
    __shared__ float t[32][33];
    const float* Ws[4] = {W0, W1, W2, W3};
    const float* W = Ws[blockIdx.z];
    __half* th = g_wth[blockIdx.z];
    __half* tl = g_wtl[blockIdx.z];
    int bx = blockIdx.x, by = blockIdx.y;
    int tid = threadIdx.x;
#pragma unroll
    for (int it = 0; it < 4; it++) {
        int idx = tid + it * 256;
        int r = idx >> 5, c = idx & 31;
        t[r][c] = W[(size_t)(by * 32 + r) * E_DIM + bx * 32 + c];
    }
    __syncthreads();
#pragma unroll
    for (int it = 0; it < 4; it++) {
        int idx = tid + it * 256;
        int r = idx >> 5, c = idx & 31;
        float x = t[c][r];
        __half h = __float2half_rn(x);
        size_t o = (size_t)(bx * 32 + r) * E_DIM + by * 32 + c;
        th[o] = h;
        tl[o] = __float2half_rn(x - __half2float(h));
    }
}

// ---------------------------------------------------------------------------
// 2-term fp16 GEMM: C = A * (Bhi + Blo). CTA 256x128, BK=64, 8 warps (4x2).
// ---------------------------------------------------------------------------
#define A_TB 36864
#define B_TB 18432
#define BUF_BYTES (A_TB + 2 * B_TB)
#define GSMEM (2 * BUF_BYTES)
#define NCHUNK 16

__device__ __forceinline__ void load_chunk_async(
    const __half* __restrict__ A,
    const __half* __restrict__ Bhi, const __half* __restrict__ Blo,
    int m0, int n0, int k0, uint32_t st, int tid) {
#pragma unroll
    for (int it = 0; it < 8; it++) {
        int idx = tid + it * 256;
        int r = idx >> 3, seg = idx & 7;
        cp_async16(st + (uint32_t)(r * 144 + seg * 16),
                   A + (size_t)(m0 + r) * E_DIM + k0 + seg * 8);
    }
#pragma unroll
    for (int it = 0; it < 4; it++) {
        int idx = tid + it * 256;
        int r = idx >> 3, seg = idx & 7;
        uint32_t off = (uint32_t)(r * 144 + seg * 16);
        const size_t go = (size_t)(n0 + r) * E_DIM + k0 + seg * 8;
        cp_async16(st + A_TB + off, Bhi + go);
        cp_async16(st + A_TB + B_TB + off, Blo + go);
    }
}

__device__ __forceinline__ void gemm_mainloop(
    const __half* __restrict__ A,
    const __half* __restrict__ Bhi, const __half* __restrict__ Blo,
    int m0, int n0, uint32_t sbase, int tid, int wm, int wn, int lane,
    float acc[4][8][4]) {

    load_chunk_async(A, Bhi, Blo, m0, n0, 0, sbase, tid);
    asm volatile("cp.async.commit_group;");

    for (int c = 0; c < NCHUNK; c++) {
        asm volatile("cp.async.wait_group 0;");
        __syncthreads();
        if (c + 1 < NCHUNK) {
            load_chunk_async(A, Bhi, Blo, m0, n0, (c + 1) << 6,
                             sbase + ((c + 1) & 1) * BUF_BYTES, tid);
            asm volatile("cp.async.commit_group;");
        }

        const uint32_t st = sbase + (c & 1) * BUF_BYTES;
        const uint32_t A_s = st;
        const uint32_t Bhi_s = st + A_TB, Blo_s = st + A_TB + B_TB;

#pragma unroll
        for (int ks = 0; ks < 4; ks++) {
            uint32_t af[4][4];
#pragma unroll
            for (int mt = 0; mt < 4; mt++) {
                int row = wm * 64 + mt * 16 + (lane & 15);
                int kb = ks * 16 + ((lane >> 4) << 3);
                ldmatrix_x4(af[mt], A_s + (uint32_t)(row * 144 + kb * 2));
            }
#pragma unroll
            for (int np = 0; np < 4; np++) {
                uint32_t bh[4], bl[4];
                int row = wn * 64 + np * 16 + ((lane >> 4) << 3) + (lane & 7);
                int kb = ks * 16 + (((lane >> 3) & 1) << 3);
                uint32_t off = (uint32_t)(row * 144 + kb * 2);
                ldmatrix_x4(bh, Bhi_s + off);
                ldmatrix_x4(bl, Blo_s + off);
#pragma unroll
                for (int half = 0; half < 2; half++)
#pragma unroll
                    for (int mt = 0; mt < 4; mt++)
                        mma16816h(acc[mt][2 * np + half], af[mt], bh + 2 * half);
#pragma unroll
                for (int half = 0; half < 2; half++)
#pragma unroll
                    for (int mt = 0; mt < 4; mt++)
                        mma16816h(acc[mt][2 * np + half], af[mt], bl + 2 * half);
            }
        }
    }
}

// Fused QKV projection: z = 0:Q(+RoPE+scale) 1:K(+RoPE) 2:V(single)
__global__ __launch_bounds__(256)
void tgemm_qkv_kernel() {
    extern __shared__ __align__(1024) char dsm[];
    const uint32_t sbase = smem_u32(dsm);
    const int tid = threadIdx.x;
    const int wid = tid >> 5, lane = tid & 31;
    const int wm = wid & 3, wn = wid >> 2;
    const int g = lane >> 2, tg = lane & 3;
    const int m0 = blockIdx.y << 8, n0 = blockIdx.x << 7;
    const int z = blockIdx.z;

    const float* bias = g_bias + (z << 10);

    float acc[4][8][4] = {};
    gemm_mainloop(g_xh, g_wth[z], g_wtl[z], m0, n0, sbase, tid, wm, wn, lane, acc);

    const int h = (n0 + wn * 64) >> 6;
#pragma unroll
    for (int mt = 0; mt < 4; mt++) {
#pragma unroll
        for (int h2 = 0; h2 < 2; h2++) {
            int m = m0 + wm * 64 + mt * 16 + g + h2 * 8;
            int bb = m >> 11, s = m & (S_LEN - 1);
            size_t rb = (((size_t)(bb * N_HEADS + h)) * S_LEN + s) << 6;
            float vals[8][2];
#pragma unroll
            for (int nt = 0; nt < 8; nt++) {
                int col = nt * 8 + tg * 2;
                float2 bv = *(const float2*)&bias[n0 + wn * 64 + col];
                vals[nt][0] = acc[mt][nt][h2 * 2 + 0] + bv.x;
                vals[nt][1] = acc[mt][nt][h2 * 2 + 1] + bv.y;
            }
            if (z < 2) {
#pragma unroll
                for (int nt = 0; nt < 4; nt++) {
#pragma unroll
                    for (int jj = 0; jj < 2; jj++) {
                        int d = nt * 8 + tg * 2 + jj;
                        float cth = g_cos[(s << 5) + d];
                        float sth = g_sin[(s << 5) + d];
                        float lo = vals[nt][jj], hi = vals[nt + 4][jj];
                        vals[nt][jj]     = fmaf(lo, cth, -hi * sth);
                        vals[nt + 4][jj] = fmaf(hi, cth,  lo * sth);
                    }
                }
            }
            if (z == 0) {
#pragma unroll
                for (int nt = 0; nt < 8; nt++) {
                    vals[nt][0] *= SCALE_Q;
                    vals[nt][1] *= SCALE_Q;
                }
            }
            if (z == 2) {
#pragma unroll
                for (int nt = 0; nt < 8; nt++) {
                    __half2 hv = __floats2half2_rn(vals[nt][0], vals[nt][1]);
                    *(__half2*)(g_vh2 + rb + nt * 8 + tg * 2) = hv;
                }
            } else {
                __half* Chi = (z == 0) ? g_qh2 : g_kh2;
                __half* Clo = (z == 0) ? g_ql2 : g_kl2;
#pragma unroll
                for (int nt = 0; nt < 8; nt++) {
                    uint32_t hv, lv;
                    split2h(vals[nt][0], vals[nt][1], hv, lv);
                    *(uint32_t*)(Chi + rb + nt * 8 + tg * 2) = hv;
                    *(uint32_t*)(Clo + rb + nt * 8 + tg * 2) = lv;
                }
            }
        }
    }
}

// Output projection
__global__ __launch_bounds__(256)
void tgemm_out_kernel(const float* __restrict__ bias, float* __restrict__ C) {
    extern __shared__ __align__(1024) char dsm[];
    const uint32_t sbase = smem_u32(dsm);
    const int tid = threadIdx.x;
    const int wid = tid >> 5, lane = tid & 31;
    const int wm = wid & 3, wn = wid >> 2;
    const int g = lane >> 2, tg = lane & 3;
    const int m0 = blockIdx.y << 8, n0 = blockIdx.x << 7;

    float acc[4][8][4] = {};
    gemm_mainloop(g_ch, g_wth[3], g_wtl[3], m0, n0, sbase, tid, wm, wn, lane, acc);

#pragma unroll
    for (int mt = 0; mt < 4; mt++) {
#pragma unroll
        for (int h2 = 0; h2 < 2; h2++) {
            int m = m0 + wm * 64 + mt * 16 + g + h2 * 8;
            float* dst = &C[(size_t)m * E_DIM + n0 + wn * 64];
#pragma unroll
            for (int nt = 0; nt < 8; nt++) {
                int col = nt * 8 + tg * 2;
                float2 bv = *(const float2*)&bias[n0 + wn * 64 + col];
                *(float2*)&dst[col] = make_float2(acc[mt][nt][h2 * 2 + 0] + bv.x,
                                                  acc[mt][nt][h2 * 2 + 1] + bv.y);
            }
        }
    }
}

// ---------------------------------------------------------------------------
// Flash attention: Q-tile 128, KV-tile 128, 8 warps, fully unrolled.
// QK 3-term fp16 (Q hi/lo x K hi/lo).  PV 1-term: P single fp16 x V single.
// ---------------------------------------------------------------------------
#define ATT_Q    0
#define ATT_QL   18432
#define ATT_BUF0 36864
#define ATT_BUFSZ 55808
#define ATT_SMEM (36864 + 2 * ATT_BUFSZ)

__device__ __forceinline__ void attn_issue_kv(
    const __half* khi, const __half* klo, const __half* v,
    const int* mask, int mask_off, uint32_t sb, int t, int tid) {
    uint32_t bufb = sb + ATT_BUF0 + (t & 1) * ATT_BUFSZ;
    int k0 = t << 7;
    const __half* srcs[3] = {khi, klo, v};
#pragma unroll
    for (int i = 0; i < 12; i++) {
        int idx = tid + i * 256;
        int arr = idx >> 10;
        int r = (idx >> 3) & 127, seg = idx & 7;
        cp_async16(bufb + arr * 18432 + (uint32_t)(r * 144 + seg * 16),
                   srcs[arr] + (size_t)(k0 + r) * HD + seg * 8);
    }
    if (tid < 32)
        cp_async16(bufb + 55296 + tid * 16, mask + mask_off + k0 + tid * 4);
}

__global__ __launch_bounds__(256)
void attn_kernel(const int* __restrict__ mask) {
    extern __shared__ __align__(1024) char sm_[];
    const uint32_t sb = smem_u32(sm_);
    const int tid = threadIdx.x, w = tid >> 5, lane = tid & 31;
    const int g = lane >> 2, tg = lane & 3;
    const int qt = gridDim.x - 1 - blockIdx.x;
    const int bh = blockIdx.y, bb = bh >> 4, hh = bh & 15;
    const int q0 = qt << 7;
    const size_t base = (size_t)bh * S_LEN * HD;

    {
        const __half* s0 = g_qh2 + base + (size_t)q0 * HD;
        const __half* s1 = g_ql2 + base + (size_t)q0 * HD;
#pragma unroll
        for (int i = 0; i < 8; i++) {
            int idx = tid + i * 256;
            int arr = idx >> 10;
            int r = (idx >> 3) & 127, seg = idx & 7;
            uint4 v = *(const uint4*)((arr ? s1 : s0) + (size_t)r * HD + seg * 8);
            *(uint4*)(sm_ + (arr ? ATT_QL : ATT_Q) + r * 144 + seg * 16) = v;
        }
    }

    const int ntile = qt + 1;
    attn_issue_kv(g_kh2 + base, g_kl2 + base, g_vh2 + base,
                  mask, bb * S_LEN, sb, 0, tid);
    asm volatile("cp.async.commit_group;");
    __syncthreads();

    uint32_t qfh[4][4], qfl[4][4];
    {
        int i = lane & 15;
        int prow = (i < 8) ? (w * 8 + i) : (64 + w * 8 + (i - 8));
        int kb = ((lane >> 4) << 3);
#pragma unroll
        for (int ks = 0; ks < 4; ks++) {
            uint32_t off = (uint32_t)(prow * 144 + (ks * 16 + kb) * 2);
            ldmatrix_x4(qfh[ks], sb + ATT_Q + off);
            ldmatrix_x4(qfl[ks], sb + ATT_QL + off);
        }
    }
    const int row0 = q0 + w * 8 + g;
    const int row1 = q0 + 64 + w * 8 + g;

    float oacc[8][4] = {};
    float l0 = 0.f, l1 = 0.f, mo0 = -1e30f, mo1 = -1e30f;

    for (int t = 0; t < ntile; t++) {
        asm volatile("cp.async.wait_group 0;");
        __syncthreads();
        if (t + 1 < ntile) {
            attn_issue_kv(g_kh2 + base, g_kl2 + base, g_vh2 + base,
                          mask, bb * S_LEN, sb, t + 1, tid);
            asm volatile("cp.async.commit_group;");
        }
        const uint32_t bufb = sb + ATT_BUF0 + (t & 1) * ATT_BUFSZ;
        const int k0 = t << 7;

        // S = Q @ K^T (3 terms, fully unrolled)
        float sc[16][4] = {};
#pragma unroll
        for (int ks = 0; ks < 4; ks++) {
#pragma unroll
            for (int ntp = 0; ntp < 8; ntp++) {
                uint32_t kh[4], kl[4];
                int row = ntp * 16 + ((lane >> 4) << 3) + (lane & 7);
                int kb = ks * 16 + (((lane >> 3) & 1) << 3);
                uint32_t off = (uint32_t)(row * 144 + kb * 2);
                ldmatrix_x4(kh, bufb + off);
                ldmatrix_x4(kl, bufb + 18432 + off);
#pragma unroll
                for (int hf = 0; hf < 2; hf++)
                    mma16816h(sc[2 * ntp + hf], qfh[ks], kh + 2 * hf);
#pragma unroll
                for (int hf = 0; hf < 2; hf++)
                    mma16816h(sc[2 * ntp + hf], qfh[ks], kl + 2 * hf);
#pragma unroll
                for (int hf = 0; hf < 2; hf++)
                    mma16816h(sc[2 * ntp + hf], qfl[ks], kh + 2 * hf);
            }
        }

        const int* Ms = (const int*)(sm_ + ATT_BUF0 + (t & 1) * ATT_BUFSZ + 55296);
        uint32_t pb[4];
        pb[0] = __ballot_sync(0xffffffffu, Ms[lane] != 0);
        pb[1] = __ballot_sync(0xffffffffu, Ms[lane + 32] != 0);
        pb[2] = __ballot_sync(0xffffffffu, Ms[lane + 64] != 0);
        pb[3] = __ballot_sync(0xffffffffu, Ms[lane + 96] != 0);
        if ((pb[0] & pb[1] & pb[2] & pb[3]) != 0xffffffffu) {
#pragma unroll
            for (int nt = 0; nt < 16; nt++)
#pragma unroll
                for (int j = 0; j < 2; j++) {
                    int cl = nt * 8 + tg * 2 + j;
                    if (!((pb[cl >> 5] >> (cl & 31)) & 1)) {
                        sc[nt][j] = -1e30f;
                        sc[nt][2 + j] = -1e30f;
                    }
                }
        }
        if (k0 + 127 > row0) {
#pragma unroll
            for (int nt = 0; nt < 16; nt++)
#pragma unroll
                for (int j = 0; j < 2; j++) {
                    int cg = k0 + nt * 8 + tg * 2 + j;
                    if (cg > row0) sc[nt][j] = -1e30f;
                    if (cg > row1) sc[nt][2 + j] = -1e30f;
                }
        }

        float mx0 = -1e30f, mx1 = -1e30f;
#pragma unroll
        for (int nt = 0; nt < 16; nt++) {
            mx0 = fmaxf(mx0, fmaxf(sc[nt][0], sc[nt][1]));
            mx1 = fmaxf(mx1, fmaxf(sc[nt][2], sc[nt][3]));
        }
        mx0 = fmaxf(mx0, __shfl_xor_sync(0xffffffffu, mx0, 1));
        mx0 = fmaxf(mx0, __shfl_xor_sync(0xffffffffu, mx0, 2));
        mx1 = fmaxf(mx1, __shfl_xor_sync(0xffffffffu, mx1, 1));
        mx1 = fmaxf(mx1, __shfl_xor_sync(0xffffffffu, mx1, 2));
        float mn0 = fmaxf(mo0, mx0), mn1 = fmaxf(mo1, mx1);
        float al0 = ex2(mo0 - mn0), al1 = ex2(mo1 - mn1);
        float rs0 = 0.f, rs1 = 0.f;
#pragma unroll
        for (int nt = 0; nt < 16; nt++) {
            sc[nt][0] = ex2(sc[nt][0] - mn0);
            sc[nt][1] = ex2(sc[nt][1] - mn0);
            sc[nt][2] = ex2(sc[nt][2] - mn1);
            sc[nt][3] = ex2(sc[nt][3] - mn1);
            rs0 += sc[nt][0] + sc[nt][1];
            rs1 += sc[nt][2] + sc[nt][3];
        }
        rs0 += __shfl_xor_sync(0xffffffffu, rs0, 1);
        rs0 += __shfl_xor_sync(0xffffffffu, rs0, 2);
        rs1 += __shfl_xor_sync(0xffffffffu, rs1, 1);
        rs1 += __shfl_xor_sync(0xffffffffu, rs1, 2);
        l0 = l0 * al0 + rs0;
        l1 = l1 * al1 + rs1;
        mo0 = mn0; mo1 = mn1;
#pragma unroll
        for (int nt = 0; nt < 8; nt++) {
            oacc[nt][0] *= al0; oacc[nt][1] *= al0;
            oacc[nt][2] *= al1; oacc[nt][3] *= al1;
        }

        // O += P @ V   (P single fp16 from registers, V single fp16)
#pragma unroll
        for (int ks = 0; ks < 8; ks++) {
            uint32_t pa[4];
            pa[0] = pack2h(sc[2 * ks][0], sc[2 * ks][1]);
            pa[1] = pack2h(sc[2 * ks][2], sc[2 * ks][3]);
            pa[2] = pack2h(sc[2 * ks + 1][0], sc[2 * ks + 1][1]);
            pa[3] = pack2h(sc[2 * ks + 1][2], sc[2 * ks + 1][3]);
#pragma unroll
            for (int dtp = 0; dtp < 4; dtp++) {
                uint32_t vh[4];
                int rkv = ks * 16 + ((lane >> 3) & 1) * 8 + (lane & 7);
                int cd = dtp * 16 + (lane >> 4) * 8;
                ldmatrix_x4_trans(vh, bufb + 36864 + (uint32_t)(rkv * 144 + cd * 2));
#pragma unroll
                for (int hf = 0; hf < 2; hf++)
                    mma16816h(oacc[2 * dtp + hf], pa, vh + 2 * hf);
            }
        }
    }

    float inv0 = 1.0f / l0, inv1 = 1.0f / l1;
    __half* d0 = g_ch + ((size_t)(bb * S_LEN + row0)) * E_DIM + hh * 64;
    __half* d1 = g_ch + ((size_t)(bb * S_LEN + row1)) * E_DIM + hh * 64;
#pragma unroll
    for (int nt = 0; nt < 8; nt++) {
        int d = nt * 8 + tg * 2;
        *(__half2*)(d0 + d) = __floats2half2_rn(oacc[nt][0] * inv0, oacc[nt][1] * inv0);
        *(__half2*)(d1 + d) = __floats2half2_rn(oacc[nt][2] * inv1, oacc[nt][3] * inv1);
    }
}

// ---------------------------------------------------------------------------
extern "C" void kernel_launch(void* const* d_in, const int* in_sizes, int n_in,
                              void* d_out, int out_size) {
    const float* x    = (const float*)d_in[0];
    const int*   mask = (const int*)d_in[1];
    const float* Wq   = (const float*)d_in[2];
    const float* bq   = (const float*)d_in[3];
    const float* Wk   = (const float*)d_in[4];
    const float* bk   = (const float*)d_in[5];
    const float* Wv   = (const float*)d_in[6];
    const float* bv   = (const float*)d_in[7];
    const float* Wo   = (const float*)d_in[8];
    const float* bo   = (const float*)d_in[9];
    float* out = (float*)d_out;

    cvt_transpose4_kernel<<<dim3(32, 32, 4), 256>>>(Wq, Wk, Wv, Wo);

    const int n4 = M_ROWS * E_DIM / 4;
    cvt_half_kernel<<<(n4 + 255) / 256, 256>>>((const float4*)x, n4, bq, bk, bv);

    cudaFuncSetAttribute(tgemm_qkv_kernel, cudaFuncAttributeMaxDynamicSharedMemorySize, GSMEM);
    cudaFuncSetAttribute(tgemm_out_kernel, cudaFuncAttributeMaxDynamicSharedMemorySize, GSMEM);
    cudaFuncSetAttribute(attn_kernel, cudaFuncAttributeMaxDynamicSharedMemorySize, ATT_SMEM);

    tgemm_qkv_kernel<<<dim3(E_DIM / 128, M_ROWS / 256, 3), 256, GSMEM>>>();

    attn_kernel<<<dim3(S_LEN / 128, BATCH * N_HEADS), 256, ATT_SMEM>>>(mask);

    tgemm_out_kernel<<<dim3(E_DIM / 128, M_ROWS / 256), 256, GSMEM>>>(bo, out);
}

// round 17
// speedup vs baseline: 1.4795x; 1.0574x over previous
#include <cuda_runtime.h>
#include <cuda_bf16.h>
#include <cuda_fp16.h>
#include <math.h>
#include <stdint.h>

#define S_LEN 2048
#define E_DIM 1024
#define N_HEADS 16
#define HD 64
#define BATCH 2
#define M_ROWS 4096
#define SCALE_Q 0.18033688011112042f   // 0.125 * log2(e)

// ---------------- scratch ---------------------------------------------------
__device__ __align__(256) float g_cos[S_LEN * 32];
__device__ __align__(256) float g_sin[S_LEN * 32];
__device__ __align__(256) float g_bias[3 * E_DIM];
__device__ __align__(256) __half g_xh[(size_t)M_ROWS * E_DIM];          // x fp16
__device__ __align__(256) __half g_ch[(size_t)M_ROWS * E_DIM];          // ctx fp16
__device__ __align__(256) __half g_wth[4][(size_t)E_DIM * E_DIM];       // W^T hi
__device__ __align__(256) __half g_wtl[3][(size_t)E_DIM * E_DIM];       // W^T lo (QKV only)
__device__ __align__(256) __half g_qh2[(size_t)M_ROWS * E_DIM];         // Q hi
__device__ __align__(256) __half g_ql2[(size_t)M_ROWS * E_DIM];         // Q lo
__device__ __align__(256) __half g_kh2[(size_t)M_ROWS * E_DIM];         // K hi
__device__ __align__(256) __half g_kl2[(size_t)M_ROWS * E_DIM];         // K lo
__device__ __align__(256) __half g_vh2[(size_t)M_ROWS * E_DIM];         // V single

// ---------------- helpers ---------------------------------------------------
__device__ __forceinline__ uint32_t smem_u32(const void* p) {
    uint32_t a;
    asm("{ .reg .u64 t; cvta.to.shared.u64 t, %1; cvt.u32.u64 %0, t; }"
        : "=r"(a) : "l"(p));
    return a;
}
__device__ __forceinline__ void ldmatrix_x4(uint32_t* r, uint32_t addr) {
    asm volatile("ldmatrix.sync.aligned.m8n8.x4.shared.b16 {%0,%1,%2,%3}, [%4];"
                 : "=r"(r[0]), "=r"(r[1]), "=r"(r[2]), "=r"(r[3]) : "r"(addr));
}
__device__ __forceinline__ void ldmatrix_x4_trans(uint32_t* r, uint32_t addr) {
    asm volatile("ldmatrix.sync.aligned.m8n8.x4.trans.shared.b16 {%0,%1,%2,%3}, [%4];"
                 : "=r"(r[0]), "=r"(r[1]), "=r"(r[2]), "=r"(r[3]) : "r"(addr));
}
__device__ __forceinline__ void mma16816h(float* c, const uint32_t* a, const uint32_t* b) {
    asm("mma.sync.aligned.m16n8k16.row.col.f32.f16.f16.f32 "
        "{%0,%1,%2,%3}, {%4,%5,%6,%7}, {%8,%9}, {%0,%1,%2,%3};"
        : "+f"(c[0]), "+f"(c[1]), "+f"(c[2]), "+f"(c[3])
        : "r"(a[0]), "r"(a[1]), "r"(a[2]), "r"(a[3]), "r"(b[0]), "r"(b[1]));
}
__device__ __forceinline__ void cp_async16(uint32_t dst, const void* src) {
    asm volatile("cp.async.cg.shared.global [%0], [%1], 16;" :: "r"(dst), "l"(src));
}
__device__ __forceinline__ float ex2(float x) {
    float y;
    asm("ex2.approx.f32 %0, %1;" : "=f"(y) : "f"(x));
    return y;
}
__device__ __forceinline__ void split2h(float x, float y, uint32_t& h, uint32_t& l) {
    __half2 hb = __floats2half2_rn(x, y);
    float2 hf = __half22float2(hb);
    __half2 lb = __floats2half2_rn(x - hf.x, y - hf.y);
    h = *(uint32_t*)&hb;
    l = *(uint32_t*)&lb;
}
__device__ __forceinline__ uint32_t pack2h(float x, float y) {
    __half2 hb = __floats2half2_rn(x, y);
    return *(uint32_t*)&hb;
}

// ---------------------------------------------------------------------------
// x: f32 -> fp16; low blocks also build rope tables + staged biases
__global__ void cvt_half_kernel(const float4* __restrict__ src, int n4,
                                const float* __restrict__ bq,
                                const float* __restrict__ bk,
                                const float* __restrict__ bv) {
    int i = blockIdx.x * blockDim.x + threadIdx.x;
    if (i < 3 * E_DIM) {
        const float* b = (i < E_DIM) ? bq : (i < 2 * E_DIM) ? bk : bv;
        g_bias[i] = b[i & (E_DIM - 1)];
    }
    if (i < S_LEN * 32) {
        int s = i >> 5, j = i & 31;
        float inv = (float)pow(10000.0, -(double)j / 32.0);
        float th = (float)s * inv;
        g_cos[i] = cosf(th);
        g_sin[i] = sinf(th);
    }
    if (i >= n4) return;
    float4 v = src[i];
    __half2* dst = (__half2*)g_xh;
    dst[2 * i]     = __floats2half2_rn(v.x, v.y);
    dst[2 * i + 1] = __floats2half2_rn(v.z, v.w);
}

// transpose + fp16 split; Wo (z==3) hi only
__global__ void cvt_transpose4_kernel(const float* __restrict__ W0,
                                      const float* __restrict__ W1,
                                      const float* __restrict__ W2,
                                      const float* __restrict__ W3) {
    __shared__ float t[32][33];
    const float* Ws[4] = {W0, W1, W2, W3};
    const int z = blockIdx.z;
    const float* W = Ws[z];
    __half* th = g_wth[z];
    __half* tl = (z < 3) ? g_wtl[z] : nullptr;
    int bx = blockIdx.x, by = blockIdx.y;
    int tid = threadIdx.x;
#pragma unroll
    for (int it = 0; it < 4; it++) {
        int idx = tid + it * 256;
        int r = idx >> 5, c = idx & 31;
        t[r][c] = W[(size_t)(by * 32 + r) * E_DIM + bx * 32 + c];
    }
    __syncthreads();
#pragma unroll
    for (int it = 0; it < 4; it++) {
        int idx = tid + it * 256;
        int r = idx >> 5, c = idx & 31;
        float x = t[c][r];
        __half h = __float2half_rn(x);
        size_t o = (size_t)(bx * 32 + r) * E_DIM + by * 32 + c;
        th[o] = h;
        if (z < 3) tl[o] = __float2half_rn(x - __half2float(h));
    }
}

// ---------------------------------------------------------------------------
// fp16 GEMM mainloop, TERMS = 2 (Bhi+Blo) or 1 (Bhi only).
// CTA 256x128, BK=64, 8 warps (4x2), warp tile 64x64, fully unrolled.
// ---------------------------------------------------------------------------
#define A_TB 36864
#define B_TB 18432
#define BUF_BYTES (A_TB + 2 * B_TB)
#define GSMEM (2 * BUF_BYTES)
#define NCHUNK 16

template <int TERMS>
__device__ __forceinline__ void load_chunk_async(
    const __half* __restrict__ A,
    const __half* __restrict__ Bhi, const __half* __restrict__ Blo,
    int m0, int n0, int k0, uint32_t st, int tid) {
#pragma unroll
    for (int it = 0; it < 8; it++) {
        int idx = tid + it * 256;
        int r = idx >> 3, seg = idx & 7;
        cp_async16(st + (uint32_t)(r * 144 + seg * 16),
                   A + (size_t)(m0 + r) * E_DIM + k0 + seg * 8);
    }
#pragma unroll
    for (int it = 0; it < 4; it++) {
        int idx = tid + it * 256;
        int r = idx >> 3, seg = idx & 7;
        uint32_t off = (uint32_t)(r * 144 + seg * 16);
        const size_t go = (size_t)(n0 + r) * E_DIM + k0 + seg * 8;
        cp_async16(st + A_TB + off, Bhi + go);
        if (TERMS == 2) cp_async16(st + A_TB + B_TB + off, Blo + go);
    }
}

template <int TERMS>
__device__ __forceinline__ void gemm_mainloop(
    const __half* __restrict__ A,
    const __half* __restrict__ Bhi, const __half* __restrict__ Blo,
    int m0, int n0, uint32_t sbase, int tid, int wm, int wn, int lane,
    float acc[4][8][4]) {

    load_chunk_async<TERMS>(A, Bhi, Blo, m0, n0, 0, sbase, tid);
    asm volatile("cp.async.commit_group;");

    for (int c = 0; c < NCHUNK; c++) {
        asm volatile("cp.async.wait_group 0;");
        __syncthreads();
        if (c + 1 < NCHUNK) {
            load_chunk_async<TERMS>(A, Bhi, Blo, m0, n0, (c + 1) << 6,
                                    sbase + ((c + 1) & 1) * BUF_BYTES, tid);
            asm volatile("cp.async.commit_group;");
        }

        const uint32_t st = sbase + (c & 1) * BUF_BYTES;
        const uint32_t A_s = st;
        const uint32_t Bhi_s = st + A_TB, Blo_s = st + A_TB + B_TB;

#pragma unroll
        for (int ks = 0; ks < 4; ks++) {
            uint32_t af[4][4];
#pragma unroll
            for (int mt = 0; mt < 4; mt++) {
                int row = wm * 64 + mt * 16 + (lane & 15);
                int kb = ks * 16 + ((lane >> 4) << 3);
                ldmatrix_x4(af[mt], A_s + (uint32_t)(row * 144 + kb * 2));
            }
#pragma unroll
            for (int np = 0; np < 4; np++) {
                uint32_t bh[4], bl[4];
                int row = wn * 64 + np * 16 + ((lane >> 4) << 3) + (lane & 7);
                int kb = ks * 16 + (((lane >> 3) & 1) << 3);
                uint32_t off = (uint32_t)(row * 144 + kb * 2);
                ldmatrix_x4(bh, Bhi_s + off);
                if (TERMS == 2) ldmatrix_x4(bl, Blo_s + off);
#pragma unroll
                for (int half = 0; half < 2; half++)
#pragma unroll
                    for (int mt = 0; mt < 4; mt++)
                        mma16816h(acc[mt][2 * np + half], af[mt], bh + 2 * half);
                if (TERMS == 2) {
#pragma unroll
                    for (int half = 0; half < 2; half++)
#pragma unroll
                        for (int mt = 0; mt < 4; mt++)
                            mma16816h(acc[mt][2 * np + half], af[mt], bl + 2 * half);
                }
            }
        }
    }
}

// Fused QKV projection: z = 0:Q(+RoPE+scale) 1:K(+RoPE) 2:V(single)
__global__ __launch_bounds__(256)
void tgemm_qkv_kernel() {
    extern __shared__ __align__(1024) char dsm[];
    const uint32_t sbase = smem_u32(dsm);
    const int tid = threadIdx.x;
    const int wid = tid >> 5, lane = tid & 31;
    const int wm = wid & 3, wn = wid >> 2;
    const int g = lane >> 2, tg = lane & 3;
    const int m0 = blockIdx.y << 8, n0 = blockIdx.x << 7;
    const int z = blockIdx.z;

    const float* bias = g_bias + (z << 10);

    float acc[4][8][4] = {};
    gemm_mainloop<2>(g_xh, g_wth[z], g_wtl[z], m0, n0, sbase, tid, wm, wn, lane, acc);

    const int h = (n0 + wn * 64) >> 6;
#pragma unroll
    for (int mt = 0; mt < 4; mt++) {
#pragma unroll
        for (int h2 = 0; h2 < 2; h2++) {
            int m = m0 + wm * 64 + mt * 16 + g + h2 * 8;
            int bb = m >> 11, s = m & (S_LEN - 1);
            size_t rb = (((size_t)(bb * N_HEADS + h)) * S_LEN + s) << 6;
            float vals[8][2];
#pragma unroll
            for (int nt = 0; nt < 8; nt++) {
                int col = nt * 8 + tg * 2;
                float2 bv = *(const float2*)&bias[n0 + wn * 64 + col];
                vals[nt][0] = acc[mt][nt][h2 * 2 + 0] + bv.x;
                vals[nt][1] = acc[mt][nt][h2 * 2 + 1] + bv.y;
            }
            if (z < 2) {
#pragma unroll
                for (int nt = 0; nt < 4; nt++) {
#pragma unroll
                    for (int jj = 0; jj < 2; jj++) {
                        int d = nt * 8 + tg * 2 + jj;
                        float cth = g_cos[(s << 5) + d];
                        float sth = g_sin[(s << 5) + d];
                        float lo = vals[nt][jj], hi = vals[nt + 4][jj];
                        vals[nt][jj]     = fmaf(lo, cth, -hi * sth);
                        vals[nt + 4][jj] = fmaf(hi, cth,  lo * sth);
                    }
                }
            }
            if (z == 0) {
#pragma unroll
                for (int nt = 0; nt < 8; nt++) {
                    vals[nt][0] *= SCALE_Q;
                    vals[nt][1] *= SCALE_Q;
                }
            }
            if (z == 2) {
#pragma unroll
                for (int nt = 0; nt < 8; nt++) {
                    __half2 hv = __floats2half2_rn(vals[nt][0], vals[nt][1]);
                    *(__half2*)(g_vh2 + rb + nt * 8 + tg * 2) = hv;
                }
            } else {
                __half* Chi = (z == 0) ? g_qh2 : g_kh2;
                __half* Clo = (z == 0) ? g_ql2 : g_kl2;
#pragma unroll
                for (int nt = 0; nt < 8; nt++) {
                    uint32_t hv, lv;
                    split2h(vals[nt][0], vals[nt][1], hv, lv);
                    *(uint32_t*)(Chi + rb + nt * 8 + tg * 2) = hv;
                    *(uint32_t*)(Clo + rb + nt * 8 + tg * 2) = lv;
                }
            }
        }
    }
}

// Output projection: 1-term (Wo single fp16)
__global__ __launch_bounds__(256)
void tgemm_out_kernel(const float* __restrict__ bias, float* __restrict__ C) {
    extern __shared__ __align__(1024) char dsm[];
    const uint32_t sbase = smem_u32(dsm);
    const int tid = threadIdx.x;
    const int wid = tid >> 5, lane = tid & 31;
    const int wm = wid & 3, wn = wid >> 2;
    const int g = lane >> 2, tg = lane & 3;
    const int m0 = blockIdx.y << 8, n0 = blockIdx.x << 7;

    float acc[4][8][4] = {};
    gemm_mainloop<1>(g_ch, g_wth[3], nullptr, m0, n0, sbase, tid, wm, wn, lane, acc);

#pragma unroll
    for (int mt = 0; mt < 4; mt++) {
#pragma unroll
        for (int h2 = 0; h2 < 2; h2++) {
            int m = m0 + wm * 64 + mt * 16 + g + h2 * 8;
            float* dst = &C[(size_t)m * E_DIM + n0 + wn * 64];
#pragma unroll
            for (int nt = 0; nt < 8; nt++) {
                int col = nt * 8 + tg * 2;
                float2 bv = *(const float2*)&bias[n0 + wn * 64 + col];
                *(float2*)&dst[col] = make_float2(acc[mt][nt][h2 * 2 + 0] + bv.x,
                                                  acc[mt][nt][h2 * 2 + 1] + bv.y);
            }
        }
    }
}

// ---------------------------------------------------------------------------
// Flash attention (R16-proven): Q-tile 128, KV-tile 128, 8 warps, fully
// unrolled. QK 3-term fp16; PV 1-term (P single x V single).
// ---------------------------------------------------------------------------
#define ATT_Q    0
#define ATT_QL   18432
#define ATT_BUF0 36864
#define ATT_BUFSZ 55808
#define ATT_SMEM (36864 + 2 * ATT_BUFSZ)

__device__ __forceinline__ void attn_issue_kv(
    const __half* khi, const __half* klo, const __half* v,
    const int* mask, int mask_off, uint32_t sb, int t, int tid) {
    uint32_t bufb = sb + ATT_BUF0 + (t & 1) * ATT_BUFSZ;
    int k0 = t << 7;
    const __half* srcs[3] = {khi, klo, v};
#pragma unroll
    for (int i = 0; i < 12; i++) {
        int idx = tid + i * 256;
        int arr = idx >> 10;
        int r = (idx >> 3) & 127, seg = idx & 7;
        cp_async16(bufb + arr * 18432 + (uint32_t)(r * 144 + seg * 16),
                   srcs[arr] + (size_t)(k0 + r) * HD + seg * 8);
    }
    if (tid < 32)
        cp_async16(bufb + 55296 + tid * 16, mask + mask_off + k0 + tid * 4);
}

__global__ __launch_bounds__(256)
void attn_kernel(const int* __restrict__ mask) {
    extern __shared__ __align__(1024) char sm_[];
    const uint32_t sb = smem_u32(sm_);
    const int tid = threadIdx.x, w = tid >> 5, lane = tid & 31;
    const int g = lane >> 2, tg = lane & 3;
    const int qt = gridDim.x - 1 - blockIdx.x;
    const int bh = blockIdx.y, bb = bh >> 4, hh = bh & 15;
    const int q0 = qt << 7;
    const size_t base = (size_t)bh * S_LEN * HD;

    {
        const __half* s0 = g_qh2 + base + (size_t)q0 * HD;
        const __half* s1 = g_ql2 + base + (size_t)q0 * HD;
#pragma unroll
        for (int i = 0; i < 8; i++) {
            int idx = tid + i * 256;
            int arr = idx >> 10;
            int r = (idx >> 3) & 127, seg = idx & 7;
            uint4 v = *(const uint4*)((arr ? s1 : s0) + (size_t)r * HD + seg * 8);
            *(uint4*)(sm_ + (arr ? ATT_QL : ATT_Q) + r * 144 + seg * 16) = v;
        }
    }

    const int ntile = qt + 1;
    attn_issue_kv(g_kh2 + base, g_kl2 + base, g_vh2 + base,
                  mask, bb * S_LEN, sb, 0, tid);
    asm volatile("cp.async.commit_group;");
    __syncthreads();

    uint32_t qfh[4][4], qfl[4][4];
    {
        int i = lane & 15;
        int prow = (i < 8) ? (w * 8 + i) : (64 + w * 8 + (i - 8));
        int kb = ((lane >> 4) << 3);
#pragma unroll
        for (int ks = 0; ks < 4; ks++) {
            uint32_t off = (uint32_t)(prow * 144 + (ks * 16 + kb) * 2);
            ldmatrix_x4(qfh[ks], sb + ATT_Q + off);
            ldmatrix_x4(qfl[ks], sb + ATT_QL + off);
        }
    }
    const int row0 = q0 + w * 8 + g;
    const int row1 = q0 + 64 + w * 8 + g;

    float oacc[8][4] = {};
    float l0 = 0.f, l1 = 0.f, mo0 = -1e30f, mo1 = -1e30f;

    for (int t = 0; t < ntile; t++) {
        asm volatile("cp.async.wait_group 0;");
        __syncthreads();
        if (t + 1 < ntile) {
            attn_issue_kv(g_kh2 + base, g_kl2 + base, g_vh2 + base,
                          mask, bb * S_LEN, sb, t + 1, tid);
            asm volatile("cp.async.commit_group;");
        }
        const uint32_t bufb = sb + ATT_BUF0 + (t & 1) * ATT_BUFSZ;
        const int k0 = t << 7;

        float sc[16][4] = {};
#pragma unroll
        for (int ks = 0; ks < 4; ks++) {
#pragma unroll
            for (int ntp = 0; ntp < 8; ntp++) {
                uint32_t kh[4], kl[4];
                int row = ntp * 16 + ((lane >> 4) << 3) + (lane & 7);
                int kb = ks * 16 + (((lane >> 3) & 1) << 3);
                uint32_t off = (uint32_t)(row * 144 + kb * 2);
                ldmatrix_x4(kh, bufb + off);
                ldmatrix_x4(kl, bufb + 18432 + off);
#pragma unroll
                for (int hf = 0; hf < 2; hf++)
                    mma16816h(sc[2 * ntp + hf], qfh[ks], kh + 2 * hf);
#pragma unroll
                for (int hf = 0; hf < 2; hf++)
                    mma16816h(sc[2 * ntp + hf], qfh[ks], kl + 2 * hf);
#pragma unroll
                for (int hf = 0; hf < 2; hf++)
                    mma16816h(sc[2 * ntp + hf], qfl[ks], kh + 2 * hf);
            }
        }

        const int* Ms = (const int*)(sm_ + ATT_BUF0 + (t & 1) * ATT_BUFSZ + 55296);
        uint32_t pb[4];
        pb[0] = __ballot_sync(0xffffffffu, Ms[lane] != 0);
        pb[1] = __ballot_sync(0xffffffffu, Ms[lane + 32] != 0);
        pb[2] = __ballot_sync(0xffffffffu, Ms[lane + 64] != 0);
        pb[3] = __ballot_sync(0xffffffffu, Ms[lane + 96] != 0);
        if ((pb[0] & pb[1] & pb[2] & pb[3]) != 0xffffffffu) {
#pragma unroll
            for (int nt = 0; nt < 16; nt++)
#pragma unroll
                for (int j = 0; j < 2; j++) {
                    int cl = nt * 8 + tg * 2 + j;
                    if (!((pb[cl >> 5] >> (cl & 31)) & 1)) {
                        sc[nt][j] = -1e30f;
                        sc[nt][2 + j] = -1e30f;
                    }
                }
        }
        if (k0 + 127 > row0) {
#pragma unroll
            for (int nt = 0; nt < 16; nt++)
#pragma unroll
                for (int j = 0; j < 2; j++) {
                    int cg = k0 + nt * 8 + tg * 2 + j;
                    if (cg > row0) sc[nt][j] = -1e30f;
                    if (cg > row1) sc[nt][2 + j] = -1e30f;
                }
        }

        float mx0 = -1e30f, mx1 = -1e30f;
#pragma unroll
        for (int nt = 0; nt < 16; nt++) {
            mx0 = fmaxf(mx0, fmaxf(sc[nt][0], sc[nt][1]));
            mx1 = fmaxf(mx1, fmaxf(sc[nt][2], sc[nt][3]));
        }
        mx0 = fmaxf(mx0, __shfl_xor_sync(0xffffffffu, mx0, 1));
        mx0 = fmaxf(mx0, __shfl_xor_sync(0xffffffffu, mx0, 2));
        mx1 = fmaxf(mx1, __shfl_xor_sync(0xffffffffu, mx1, 1));
        mx1 = fmaxf(mx1, __shfl_xor_sync(0xffffffffu, mx1, 2));
        float mn0 = fmaxf(mo0, mx0), mn1 = fmaxf(mo1, mx1);
        float al0 = ex2(mo0 - mn0), al1 = ex2(mo1 - mn1);
        float rs0 = 0.f, rs1 = 0.f;
#pragma unroll
        for (int nt = 0; nt < 16; nt++) {
            sc[nt][0] = ex2(sc[nt][0] - mn0);
            sc[nt][1] = ex2(sc[nt][1] - mn0);
            sc[nt][2] = ex2(sc[nt][2] - mn1);
            sc[nt][3] = ex2(sc[nt][3] - mn1);
            rs0 += sc[nt][0] + sc[nt][1];
            rs1 += sc[nt][2] + sc[nt][3];
        }
        rs0 += __shfl_xor_sync(0xffffffffu, rs0, 1);
        rs0 += __shfl_xor_sync(0xffffffffu, rs0, 2);
        rs1 += __shfl_xor_sync(0xffffffffu, rs1, 1);
        rs1 += __shfl_xor_sync(0xffffffffu, rs1, 2);
        l0 = l0 * al0 + rs0;
        l1 = l1 * al1 + rs1;
        mo0 = mn0; mo1 = mn1;
#pragma unroll
        for (int nt = 0; nt < 8; nt++) {
            oacc[nt][0] *= al0; oacc[nt][1] *= al0;
            oacc[nt][2] *= al1; oacc[nt][3] *= al1;
        }

#pragma unroll
        for (int ks = 0; ks < 8; ks++) {
            uint32_t pa[4];
            pa[0] = pack2h(sc[2 * ks][0], sc[2 * ks][1]);
            pa[1] = pack2h(sc[2 * ks][2], sc[2 * ks][3]);
            pa[2] = pack2h(sc[2 * ks + 1][0], sc[2 * ks + 1][1]);
            pa[3] = pack2h(sc[2 * ks + 1][2], sc[2 * ks + 1][3]);
#pragma unroll
            for (int dtp = 0; dtp < 4; dtp++) {
                uint32_t vh[4];
                int rkv = ks * 16 + ((lane >> 3) & 1) * 8 + (lane & 7);
                int cd = dtp * 16 + (lane >> 4) * 8;
                ldmatrix_x4_trans(vh, bufb + 36864 + (uint32_t)(rkv * 144 + cd * 2));
#pragma unroll
                for (int hf = 0; hf < 2; hf++)
                    mma16816h(oacc[2 * dtp + hf], pa, vh + 2 * hf);
            }
        }
    }

    float inv0 = 1.0f / l0, inv1 = 1.0f / l1;
    __half* d0 = g_ch + ((size_t)(bb * S_LEN + row0)) * E_DIM + hh * 64;
    __half* d1 = g_ch + ((size_t)(bb * S_LEN + row1)) * E_DIM + hh * 64;
#pragma unroll
    for (int nt = 0; nt < 8; nt++) {
        int d = nt * 8 + tg * 2;
        *(__half2*)(d0 + d) = __floats2half2_rn(oacc[nt][0] * inv0, oacc[nt][1] * inv0);
        *(__half2*)(d1 + d) = __floats2half2_rn(oacc[nt][2] * inv1, oacc[nt][3] * inv1);
    }
}

// ---------------------------------------------------------------------------
extern "C" void kernel_launch(void* const* d_in, const int* in_sizes, int n_in,
                              void* d_out, int out_size) {
    const float* x    = (const float*)d_in[0];
    const int*   mask = (const int*)d_in[1];
    const float* Wq   = (const float*)d_in[2];
    const float* bq   = (const float*)d_in[3];
    const float* Wk   = (const float*)d_in[4];
    const float* bk   = (const float*)d_in[5];
    const float* Wv   = (const float*)d_in[6];
    const float* bv   = (const float*)d_in[7];
    const float* Wo   = (const float*)d_in[8];
    const float* bo   = (const float*)d_in[9];
    float* out = (float*)d_out;

    cvt_transpose4_kernel<<<dim3(32, 32, 4), 256>>>(Wq, Wk, Wv, Wo);

    const int n4 = M_ROWS * E_DIM / 4;
    cvt_half_kernel<<<(n4 + 255) / 256, 256>>>((const float4*)x, n4, bq, bk, bv);

    cudaFuncSetAttribute(tgemm_qkv_kernel, cudaFuncAttributeMaxDynamicSharedMemorySize, GSMEM);
    cudaFuncSetAttribute(tgemm_out_kernel, cudaFuncAttributeMaxDynamicSharedMemorySize, GSMEM);
    cudaFuncSetAttribute(attn_kernel, cudaFuncAttributeMaxDynamicSharedMemorySize, ATT_SMEM);

    tgemm_qkv_kernel<<<dim3(E_DIM / 128, M_ROWS / 256, 3), 256, GSMEM>>>();

    attn_kernel<<<dim3(S_LEN / 128, BATCH * N_HEADS), 256, ATT_SMEM>>>(mask);

    tgemm_out_kernel<<<dim3(E_DIM / 128, M_ROWS / 256), 256, GSMEM>>>(bo, out);
}